// round 1
// baseline (speedup 1.0000x reference)
#include <cuda_runtime.h>
#include <math.h>

#define B_   2
#define TT_  128
#define TA_  512
#define H_   1024
#define EPS_ 1e-5f

// ---------------- scratch (no allocations allowed) ----------------
__device__ float g_tpart[B_ * TT_ * H_];   // text @ a_w1[:H] + a_b1
__device__ float g_apart[B_ * TA_ * H_];   // audio @ a_w1[H:]
__device__ float g_x1[B_ * TT_ * H_];      // relu(conv1)
__device__ float g_x2[B_ * TT_ * H_];      // relu(conv2)
__device__ float g_logits[B_ * TT_ * TA_];
__device__ float g_stats[8];               // [gn1 b0 mu,rstd, gn1 b1 mu,rstd, gn2 ...]
__device__ float g_w1t[3 * H_ * H_];       // d_w1 transposed to [k][i][o]
__device__ float g_w2t[3 * H_ * H_];

// ---------------- weight transpose [O][I][3] -> [3][I][O] ----------------
__global__ void transpose_w_k(const float* __restrict__ W, float* __restrict__ Wt) {
    __shared__ float s[32][97];
    int o0 = blockIdx.x * 32;
    int i0 = blockIdx.y * 32;
    int tx = threadIdx.x, ty = threadIdx.y;
    // read 32 rows (o) x 96 consecutive floats (32 i * 3 k)
    for (int rr = ty; rr < 32; rr += 8)
        for (int cc = tx; cc < 96; cc += 32)
            s[rr][cc] = W[(o0 + rr) * 3 * H_ + i0 * 3 + cc];
    __syncthreads();
    // write [k][i][o], coalesced over o (= tx)
    for (int il = ty; il < 32; il += 8) {
#pragma unroll
        for (int k = 0; k < 3; k++)
            Wt[k * H_ * H_ + (i0 + il) * H_ + o0 + tx] = s[tx][il * 3 + k];
    }
}

// ---------------- plain GEMM: C[M,N] = act(A[M,K] @ Bw[K,N] + bias) --------
// tiles 32x64, TK=16, 256 threads, 2x4 micro. M%32==0, N%64==0, K%16==0.
template <bool BIAS, bool RELU>
__global__ void gemm_k(const float* __restrict__ A, const float* __restrict__ Bw,
                       const float* __restrict__ bias, float* __restrict__ C,
                       int M, int N, int K) {
    __shared__ __align__(16) float As[32][17];
    __shared__ __align__(16) float Bs[16][64];
    int tid = threadIdx.x;
    int m0 = blockIdx.y * 32;
    int n0 = blockIdx.x * 64;
    int ty = tid >> 4;  // 0..15
    int tx = tid & 15;  // 0..15
    float acc[2][4] = {};
    for (int k0 = 0; k0 < K; k0 += 16) {
#pragma unroll
        for (int l = 0; l < 2; l++) {
            int idx = tid + l * 256;
            int r = idx >> 4, c = idx & 15;
            As[r][c] = A[(m0 + r) * K + k0 + c];
        }
#pragma unroll
        for (int l = 0; l < 4; l++) {
            int idx = tid + l * 256;
            int r = idx >> 6, c = idx & 63;
            Bs[r][c] = Bw[(k0 + r) * N + n0 + c];
        }
        __syncthreads();
#pragma unroll
        for (int kk = 0; kk < 16; kk++) {
            float4 bv = *reinterpret_cast<const float4*>(&Bs[kk][tx * 4]);
            float a0 = As[ty * 2 + 0][kk];
            float a1 = As[ty * 2 + 1][kk];
            acc[0][0] += a0 * bv.x; acc[0][1] += a0 * bv.y;
            acc[0][2] += a0 * bv.z; acc[0][3] += a0 * bv.w;
            acc[1][0] += a1 * bv.x; acc[1][1] += a1 * bv.y;
            acc[1][2] += a1 * bv.z; acc[1][3] += a1 * bv.w;
        }
        __syncthreads();
    }
#pragma unroll
    for (int i = 0; i < 2; i++) {
        int m = m0 + ty * 2 + i;
#pragma unroll
        for (int j = 0; j < 4; j++) {
            int n = n0 + tx * 4 + j;
            float v = acc[i][j];
            if (BIAS) v += bias[n];
            if (RELU) v = fmaxf(v, 0.f);
            C[m * N + n] = v;
        }
    }
}

// ---------------- conv1d(H,H,3) as 3 shifted GEMMs, optional GN on load ----
// Y[bt,o] = relu( bias[o] + sum_k sum_i gn(X[bt+k-1, i]) * Wt[k][i][o] )
template <bool GN>
__global__ void conv3_gemm_k(const float* __restrict__ X, const float* __restrict__ Wt,
                             const float* __restrict__ bias,
                             const float* __restrict__ gng, const float* __restrict__ gnb,
                             const float* __restrict__ stats,
                             float* __restrict__ Y) {
    __shared__ __align__(16) float As[32][17];
    __shared__ __align__(16) float Bs[16][64];
    int tid = threadIdx.x;
    int m0 = blockIdx.y * 32;
    int n0 = blockIdx.x * 64;
    int ty = tid >> 4, tx = tid & 15;
    float acc[2][4] = {};
    for (int k = 0; k < 3; k++) {
        const float* Wk = Wt + k * H_ * H_;
        for (int k0 = 0; k0 < H_; k0 += 16) {
#pragma unroll
            for (int l = 0; l < 2; l++) {
                int idx = tid + l * 256;
                int r = idx >> 4, c = idx & 15;
                int bt = m0 + r;
                int b = bt / TT_, t = bt % TT_;
                int tp = t + k - 1;
                float v = 0.f;
                if (tp >= 0 && tp < TT_) {
                    int col = k0 + c;
                    v = X[(b * TT_ + tp) * H_ + col];
                    if (GN) {
                        float mu = stats[b * 2], rstd = stats[b * 2 + 1];
                        v = (v - mu) * rstd * gng[col] + gnb[col];
                    }
                }
                As[r][c] = v;
            }
#pragma unroll
            for (int l = 0; l < 4; l++) {
                int idx = tid + l * 256;
                int r = idx >> 6, c = idx & 63;
                Bs[r][c] = Wk[(k0 + r) * H_ + n0 + c];
            }
            __syncthreads();
#pragma unroll
            for (int kk = 0; kk < 16; kk++) {
                float4 bv = *reinterpret_cast<const float4*>(&Bs[kk][tx * 4]);
                float a0 = As[ty * 2 + 0][kk];
                float a1 = As[ty * 2 + 1][kk];
                acc[0][0] += a0 * bv.x; acc[0][1] += a0 * bv.y;
                acc[0][2] += a0 * bv.z; acc[0][3] += a0 * bv.w;
                acc[1][0] += a1 * bv.x; acc[1][1] += a1 * bv.y;
                acc[1][2] += a1 * bv.z; acc[1][3] += a1 * bv.w;
            }
            __syncthreads();
        }
    }
#pragma unroll
    for (int i = 0; i < 2; i++) {
        int m = m0 + ty * 2 + i;
#pragma unroll
        for (int j = 0; j < 4; j++) {
            int n = n0 + tx * 4 + j;
            float v = acc[i][j] + bias[n];
            Y[m * H_ + n] = fmaxf(v, 0.f);
        }
    }
}

// ---------------- per-batch mean / rstd over (C,T) = TT*H values ----------
__global__ void stats_k(const float* __restrict__ X, float* __restrict__ stats) {
    __shared__ float sh[64];
    int b = blockIdx.x;
    const float* p = X + b * TT_ * H_;
    float s = 0.f, sq = 0.f;
    for (int i = threadIdx.x; i < TT_ * H_; i += blockDim.x) {
        float v = p[i];
        s += v; sq += v * v;
    }
#pragma unroll
    for (int o = 16; o; o >>= 1) {
        s += __shfl_xor_sync(0xffffffffu, s, o);
        sq += __shfl_xor_sync(0xffffffffu, sq, o);
    }
    int w = threadIdx.x >> 5, l = threadIdx.x & 31;
    if (l == 0) { sh[w] = s; sh[32 + w] = sq; }
    __syncthreads();
    if (threadIdx.x == 0) {
        int nw = blockDim.x >> 5;
        float ss = 0.f, ssq = 0.f;
        for (int i = 0; i < nw; i++) { ss += sh[i]; ssq += sh[32 + i]; }
        float inv = 1.0f / (float)(TT_ * H_);
        float mu = ss * inv;
        float var = ssq * inv - mu * mu;
        stats[b * 2] = mu;
        stats[b * 2 + 1] = rsqrtf(var + EPS_);
    }
}

// ---------------- fused logits: L[b,t,a] = sum_h relu(T+A)*w2 + b2 + bias --
// tile 16 t x 64 a, 256 threads, 2x2 micro strided (rows ty,ty+8 ; cols tx,tx+32)
__global__ void logits_k(const float* __restrict__ tpart, const float* __restrict__ apart,
                         const float* __restrict__ w2, const float* __restrict__ b2,
                         float* __restrict__ L) {
    __shared__ __align__(16) float Ts[16][33];
    __shared__ __align__(16) float Am[64][33];
    __shared__ float ws[32];
    int b = blockIdx.z;
    int t0 = blockIdx.y * 16;
    int a0 = blockIdx.x * 64;
    int tid = threadIdx.x;
    int ty = tid >> 5;  // 0..7
    int tx = tid & 31;  // 0..31
    float acc[2][2] = {};
    const float* Tp = tpart + (b * TT_ + t0) * H_;
    const float* Ap = apart + (b * TA_ + a0) * H_;
    for (int h0 = 0; h0 < H_; h0 += 32) {
#pragma unroll
        for (int l = 0; l < 2; l++) {
            int idx = tid + l * 256;
            int r = idx >> 5, c = idx & 31;
            Ts[r][c] = Tp[r * H_ + h0 + c];
        }
#pragma unroll
        for (int l = 0; l < 8; l++) {
            int idx = tid + l * 256;
            int r = idx >> 5, c = idx & 31;
            Am[r][c] = Ap[r * H_ + h0 + c];
        }
        if (tid < 32) ws[tid] = w2[h0 + tid];
        __syncthreads();
#pragma unroll
        for (int hh = 0; hh < 32; hh++) {
            float w = ws[hh];
            float tv0 = Ts[ty][hh], tv1 = Ts[ty + 8][hh];
            float av0 = Am[tx][hh], av1 = Am[tx + 32][hh];
            acc[0][0] += fmaxf(tv0 + av0, 0.f) * w;
            acc[0][1] += fmaxf(tv0 + av1, 0.f) * w;
            acc[1][0] += fmaxf(tv1 + av0, 0.f) * w;
            acc[1][1] += fmaxf(tv1 + av1, 0.f) * w;
        }
        __syncthreads();
    }
    float bb = b2[0];
#pragma unroll
    for (int i = 0; i < 2; i++) {
        int t = t0 + ty + i * 8;
#pragma unroll
        for (int j = 0; j < 2; j++) {
            int a = a0 + tx + j * 32;
            float bias = -0.1f * fabsf((float)a - (float)t * 4.0f);
            L[(b * TT_ + t) * TA_ + a] = acc[i][j] + bb + bias;
        }
    }
}

// ---------------- softmax over TA=512 per (b,t) row ----------------
__global__ void softmax_k(const float* __restrict__ L, float* __restrict__ out) {
    __shared__ float wred[16];
    __shared__ float s_bcast;
    int row = blockIdx.x;
    int tid = threadIdx.x;  // 512
    float v = L[row * TA_ + tid];
    float m = v;
#pragma unroll
    for (int o = 16; o; o >>= 1) m = fmaxf(m, __shfl_xor_sync(0xffffffffu, m, o));
    if ((tid & 31) == 0) wred[tid >> 5] = m;
    __syncthreads();
    if (tid == 0) {
        float mm = wred[0];
        for (int i = 1; i < 16; i++) mm = fmaxf(mm, wred[i]);
        s_bcast = mm;
    }
    __syncthreads();
    float mx = s_bcast;
    float e = expf(v - mx);
    float s = e;
#pragma unroll
    for (int o = 16; o; o >>= 1) s += __shfl_xor_sync(0xffffffffu, s, o);
    if ((tid & 31) == 0) wred[tid >> 5] = s;
    __syncthreads();
    if (tid == 0) {
        float ss = 0.f;
        for (int i = 0; i < 16; i++) ss += wred[i];
        s_bcast = ss;
    }
    __syncthreads();
    out[row * TA_ + tid] = e / s_bcast;
}

// ---------------- conv3 (H->1,k=1) on gn2(x2) + softplus ----------------
__global__ void dur_k(const float* __restrict__ X2, const float* __restrict__ w3,
                      const float* __restrict__ b3,
                      const float* __restrict__ gng, const float* __restrict__ gnb,
                      const float* __restrict__ stats, float* __restrict__ out) {
    __shared__ float wred[8];
    int bt = blockIdx.x;
    int b = bt / TT_;
    float mu = stats[b * 2], rstd = stats[b * 2 + 1];
    const float* x = X2 + bt * H_;
    int tid = threadIdx.x;  // 256
    float s = 0.f;
    for (int i = tid; i < H_; i += 256) {
        float v = (x[i] - mu) * rstd * gng[i] + gnb[i];
        s += v * w3[i];
    }
#pragma unroll
    for (int o = 16; o; o >>= 1) s += __shfl_xor_sync(0xffffffffu, s, o);
    if ((tid & 31) == 0) wred[tid >> 5] = s;
    __syncthreads();
    if (tid == 0) {
        float ss = 0.f;
        for (int i = 0; i < 8; i++) ss += wred[i];
        float z = ss + b3[0];
        out[bt] = fmaxf(z, 0.f) + log1pf(expf(-fabsf(z)));
    }
}

// ---------------- launch ----------------
extern "C" void kernel_launch(void* const* d_in, const int* in_sizes, int n_in,
                              void* d_out, int out_size) {
    (void)in_sizes; (void)n_in; (void)out_size;
    const float* text  = (const float*)d_in[0];
    const float* audio = (const float*)d_in[1];
    const float* a_w1  = (const float*)d_in[2];
    const float* a_b1  = (const float*)d_in[3];
    const float* a_w2  = (const float*)d_in[4];
    const float* a_b2  = (const float*)d_in[5];
    const float* d_w1  = (const float*)d_in[6];
    const float* d_b1  = (const float*)d_in[7];
    const float* gn1g  = (const float*)d_in[8];
    const float* gn1b  = (const float*)d_in[9];
    const float* d_w2  = (const float*)d_in[10];
    const float* d_b2  = (const float*)d_in[11];
    const float* gn2g  = (const float*)d_in[12];
    const float* gn2b  = (const float*)d_in[13];
    const float* d_w3  = (const float*)d_in[14];
    const float* d_b3  = (const float*)d_in[15];
    float* out = (float*)d_out;

    float *tpart, *apart, *x1, *x2, *logits, *stats, *w1t, *w2t;
    cudaGetSymbolAddress((void**)&tpart,  g_tpart);
    cudaGetSymbolAddress((void**)&apart,  g_apart);
    cudaGetSymbolAddress((void**)&x1,     g_x1);
    cudaGetSymbolAddress((void**)&x2,     g_x2);
    cudaGetSymbolAddress((void**)&logits, g_logits);
    cudaGetSymbolAddress((void**)&stats,  g_stats);
    cudaGetSymbolAddress((void**)&w1t,    g_w1t);
    cudaGetSymbolAddress((void**)&w2t,    g_w2t);

    // ---- weight transposes (for conv GEMM coalescing) ----
    dim3 tb(32, 8);
    dim3 tg(H_ / 32, H_ / 32);
    transpose_w_k<<<tg, tb>>>(d_w1, w1t);
    transpose_w_k<<<tg, tb>>>(d_w2, w2t);

    // ---- alignment path ----
    // t_part = text @ a_w1[:H] + a_b1   (M=256, N=1024, K=1024)
    gemm_k<true, false><<<dim3(H_ / 64, (B_ * TT_) / 32), 256>>>(
        text, a_w1, a_b1, tpart, B_ * TT_, H_, H_);
    // a_part = audio @ a_w1[H:]         (M=1024, N=1024, K=1024)
    gemm_k<false, false><<<dim3(H_ / 64, (B_ * TA_) / 32), 256>>>(
        audio, a_w1 + H_ * H_, nullptr, apart, B_ * TA_, H_, H_);
    // fused logits (+ a_b2 + monotonic bias)
    logits_k<<<dim3(TA_ / 64, TT_ / 16, B_), 256>>>(tpart, apart, a_w2, a_b2, logits);
    // softmax -> alignment output
    softmax_k<<<B_ * TT_, TA_>>>(logits, out);

    // ---- duration path ----
    conv3_gemm_k<false><<<dim3(H_ / 64, (B_ * TT_) / 32), 256>>>(
        text, w1t, d_b1, nullptr, nullptr, nullptr, x1);
    stats_k<<<B_, 512>>>(x1, stats);                 // gn1 stats at stats[0..3]
    conv3_gemm_k<true><<<dim3(H_ / 64, (B_ * TT_) / 32), 256>>>(
        x1, w2t, d_b2, gn1g, gn1b, stats, x2);
    stats_k<<<B_, 512>>>(x2, stats + 4);             // gn2 stats at stats[4..7]
    dur_k<<<B_ * TT_, 256>>>(x2, d_w3, d_b3, gn2g, gn2b, stats + 4,
                             out + B_ * TT_ * TA_);
}

// round 2
// speedup vs baseline: 1.1131x; 1.1131x over previous
#include <cuda_runtime.h>
#include <math.h>

#define B_   2
#define TT_  128
#define TA_  512
#define H_   1024
#define EPS_ 1e-5f

typedef unsigned long long u64;

// ---------------- packed fp32x2 helpers (sm_103a FFMA2 path) ----------------
__device__ __forceinline__ u64 pack2(float lo, float hi) {
    u64 r; asm("mov.b64 %0, {%1,%2};" : "=l"(r) : "f"(lo), "f"(hi)); return r;
}
__device__ __forceinline__ u64 pack_dup(float a) {
    u64 r; asm("mov.b64 %0, {%1,%1};" : "=l"(r) : "f"(a)); return r;
}
__device__ __forceinline__ float2 unpack2(u64 v) {
    float2 f; asm("mov.b64 {%0,%1}, %2;" : "=f"(f.x), "=f"(f.y) : "l"(v)); return f;
}
__device__ __forceinline__ void ffma2(u64& acc, u64 a, u64 b) {
    asm("fma.rn.f32x2 %0, %1, %2, %0;" : "+l"(acc) : "l"(a), "l"(b));
}

// ---------------- scratch (no allocations allowed) ----------------
__device__ float g_tpart[B_ * TT_ * H_];
__device__ float g_apart[B_ * TA_ * H_];
__device__ float g_x1[B_ * TT_ * H_];      // relu(conv1)
__device__ float g_xn[B_ * TT_ * H_];      // gn1(x1)
__device__ float g_x2[B_ * TT_ * H_];      // relu(conv2)
__device__ float g_logits[B_ * TT_ * TA_];
__device__ float g_stats[8];
__device__ float g_w1t[3 * H_ * H_];       // [k][i][o]
__device__ float g_w2t[3 * H_ * H_];

// ---------------- weight transpose [O][I][3] -> [3][I][O] ----------------
__global__ void transpose_w_k(const float* __restrict__ W, float* __restrict__ Wt) {
    __shared__ float s[32][97];
    int o0 = blockIdx.x * 32;
    int i0 = blockIdx.y * 32;
    int tx = threadIdx.x, ty = threadIdx.y;
    for (int rr = ty; rr < 32; rr += 8)
        for (int cc = tx; cc < 96; cc += 32)
            s[rr][cc] = W[(o0 + rr) * 3 * H_ + i0 * 3 + cc];
    __syncthreads();
    for (int il = ty; il < 32; il += 8) {
#pragma unroll
        for (int k = 0; k < 3; k++)
            Wt[k * H_ * H_ + (i0 + il) * H_ + o0 + tx] = s[tx][il * 3 + k];
    }
}

// ---------------- GEMM 64x64 tile, TK=16, 256 thr, 4x4 micro, FFMA2 --------
// C[M,N] = A[M,K] @ Bw[K,N] (+bias)(relu). M%64==0, N%64==0, K%16==0.
template <bool BIAS, bool RELU>
__global__ void gemm64_k(const float* __restrict__ A, const float* __restrict__ Bw,
                         const float* __restrict__ bias, float* __restrict__ C,
                         int M, int N, int K) {
    __shared__ __align__(16) float As[16][68];   // [k][m]
    __shared__ __align__(16) float Bs[16][64];   // [k][n]
    int tid = threadIdx.x;
    int m0 = blockIdx.y * 64;
    int n0 = blockIdx.x * 64;
    int tm = tid >> 4;   // 0..15 (m group)
    int tn = tid & 15;   // 0..15 (n group)
    // A loader: 64 rows x 16 k; thread: row ar, 4 k at ac
    int ar = tid >> 2;
    int ac = (tid & 3) * 4;
    // B loader: 16 rows x 64 n; thread: row br, 4 n at bc
    int br = tid >> 4;
    int bc = (tid & 15) * 4;

    u64 acc[4][2] = {};
    for (int k0 = 0; k0 < K; k0 += 16) {
        float4 a4 = *reinterpret_cast<const float4*>(&A[(m0 + ar) * K + k0 + ac]);
        As[ac + 0][ar] = a4.x;
        As[ac + 1][ar] = a4.y;
        As[ac + 2][ar] = a4.z;
        As[ac + 3][ar] = a4.w;
        float4 b4 = *reinterpret_cast<const float4*>(&Bw[(k0 + br) * N + n0 + bc]);
        *reinterpret_cast<float4*>(&Bs[br][bc]) = b4;
        __syncthreads();
#pragma unroll
        for (int kk = 0; kk < 16; kk++) {
            float4 av = *reinterpret_cast<const float4*>(&As[kk][tm * 4]);
            ulonglong2 bv = *reinterpret_cast<const ulonglong2*>(&Bs[kk][tn * 4]);
            u64 a0 = pack_dup(av.x), a1 = pack_dup(av.y);
            u64 a2 = pack_dup(av.z), a3 = pack_dup(av.w);
            ffma2(acc[0][0], a0, bv.x); ffma2(acc[0][1], a0, bv.y);
            ffma2(acc[1][0], a1, bv.x); ffma2(acc[1][1], a1, bv.y);
            ffma2(acc[2][0], a2, bv.x); ffma2(acc[2][1], a2, bv.y);
            ffma2(acc[3][0], a3, bv.x); ffma2(acc[3][1], a3, bv.y);
        }
        __syncthreads();
    }
    int n = n0 + tn * 4;
    float4 bv = BIAS ? *reinterpret_cast<const float4*>(&bias[n])
                     : make_float4(0.f, 0.f, 0.f, 0.f);
#pragma unroll
    for (int i = 0; i < 4; i++) {
        float2 p0 = unpack2(acc[i][0]);
        float2 p1 = unpack2(acc[i][1]);
        float4 v = make_float4(p0.x + bv.x, p0.y + bv.y, p1.x + bv.z, p1.y + bv.w);
        if (RELU) {
            v.x = fmaxf(v.x, 0.f); v.y = fmaxf(v.y, 0.f);
            v.z = fmaxf(v.z, 0.f); v.w = fmaxf(v.w, 0.f);
        }
        *reinterpret_cast<float4*>(&C[(m0 + tm * 4 + i) * N + n]) = v;
    }
}

// ---------------- GEMM 32x64 tile, TK=16, 256 thr, 2x4 micro, FFMA2 --------
template <bool BIAS, bool RELU>
__global__ void gemm32_k(const float* __restrict__ A, const float* __restrict__ Bw,
                         const float* __restrict__ bias, float* __restrict__ C,
                         int M, int N, int K) {
    __shared__ __align__(16) float As[16][36];
    __shared__ __align__(16) float Bs[16][64];
    int tid = threadIdx.x;
    int m0 = blockIdx.y * 32;
    int n0 = blockIdx.x * 64;
    int tm = tid >> 4;
    int tn = tid & 15;
    int ar = tid >> 3;          // 0..31
    int ac = (tid & 7) * 2;     // 0..14
    int br = tid >> 4;
    int bc = (tid & 15) * 4;

    u64 acc[2][2] = {};
    for (int k0 = 0; k0 < K; k0 += 16) {
        float2 a2 = *reinterpret_cast<const float2*>(&A[(m0 + ar) * K + k0 + ac]);
        As[ac + 0][ar] = a2.x;
        As[ac + 1][ar] = a2.y;
        float4 b4 = *reinterpret_cast<const float4*>(&Bw[(k0 + br) * N + n0 + bc]);
        *reinterpret_cast<float4*>(&Bs[br][bc]) = b4;
        __syncthreads();
#pragma unroll
        for (int kk = 0; kk < 16; kk++) {
            float a0 = As[kk][tm * 2 + 0];
            float a1 = As[kk][tm * 2 + 1];
            ulonglong2 bv = *reinterpret_cast<const ulonglong2*>(&Bs[kk][tn * 4]);
            u64 A0 = pack_dup(a0), A1 = pack_dup(a1);
            ffma2(acc[0][0], A0, bv.x); ffma2(acc[0][1], A0, bv.y);
            ffma2(acc[1][0], A1, bv.x); ffma2(acc[1][1], A1, bv.y);
        }
        __syncthreads();
    }
    int n = n0 + tn * 4;
    float4 bv = BIAS ? *reinterpret_cast<const float4*>(&bias[n])
                     : make_float4(0.f, 0.f, 0.f, 0.f);
#pragma unroll
    for (int i = 0; i < 2; i++) {
        float2 p0 = unpack2(acc[i][0]);
        float2 p1 = unpack2(acc[i][1]);
        float4 v = make_float4(p0.x + bv.x, p0.y + bv.y, p1.x + bv.z, p1.y + bv.w);
        if (RELU) {
            v.x = fmaxf(v.x, 0.f); v.y = fmaxf(v.y, 0.f);
            v.z = fmaxf(v.z, 0.f); v.w = fmaxf(v.w, 0.f);
        }
        *reinterpret_cast<float4*>(&C[(m0 + tm * 2 + i) * N + n]) = v;
    }
}

// ---------------- conv1d(H,H,3): 3 shifted GEMMs, 32x64 tile, FFMA2 --------
// Y[bt,o] = relu(bias[o] + sum_k sum_i X[bt+k-1,i] * Wt[k][i][o])
__global__ void conv3_k(const float* __restrict__ X, const float* __restrict__ Wt,
                        const float* __restrict__ bias, float* __restrict__ Y) {
    __shared__ __align__(16) float As[16][36];
    __shared__ __align__(16) float Bs[16][64];
    int tid = threadIdx.x;
    int m0 = blockIdx.y * 32;
    int n0 = blockIdx.x * 64;
    int tm = tid >> 4;
    int tn = tid & 15;
    int ar = tid >> 3;
    int ac = (tid & 7) * 2;
    int br = tid >> 4;
    int bc = (tid & 15) * 4;

    int bt = m0 + ar;
    int b = bt >> 7;           // /TT_
    int tloc = bt & 127;

    u64 acc[2][2] = {};
    for (int k = 0; k < 3; k++) {
        const float* Wk = Wt + k * H_ * H_;
        int tp = tloc + k - 1;
        bool inb = (tp >= 0) && (tp < TT_);
        const float* Xrow = X + (b * TT_ + (inb ? tp : 0)) * H_;
        for (int k0 = 0; k0 < H_; k0 += 16) {
            float2 a2 = make_float2(0.f, 0.f);
            if (inb) a2 = *reinterpret_cast<const float2*>(&Xrow[k0 + ac]);
            As[ac + 0][ar] = a2.x;
            As[ac + 1][ar] = a2.y;
            float4 b4 = *reinterpret_cast<const float4*>(&Wk[(k0 + br) * H_ + n0 + bc]);
            *reinterpret_cast<float4*>(&Bs[br][bc]) = b4;
            __syncthreads();
#pragma unroll
            for (int kk = 0; kk < 16; kk++) {
                float a0 = As[kk][tm * 2 + 0];
                float a1 = As[kk][tm * 2 + 1];
                ulonglong2 bv = *reinterpret_cast<const ulonglong2*>(&Bs[kk][tn * 4]);
                u64 A0 = pack_dup(a0), A1 = pack_dup(a1);
                ffma2(acc[0][0], A0, bv.x); ffma2(acc[0][1], A0, bv.y);
                ffma2(acc[1][0], A1, bv.x); ffma2(acc[1][1], A1, bv.y);
            }
            __syncthreads();
        }
    }
    int n = n0 + tn * 4;
    float4 bvb = *reinterpret_cast<const float4*>(&bias[n]);
#pragma unroll
    for (int i = 0; i < 2; i++) {
        float2 p0 = unpack2(acc[i][0]);
        float2 p1 = unpack2(acc[i][1]);
        float4 v = make_float4(fmaxf(p0.x + bvb.x, 0.f), fmaxf(p0.y + bvb.y, 0.f),
                               fmaxf(p1.x + bvb.z, 0.f), fmaxf(p1.y + bvb.w, 0.f));
        *reinterpret_cast<float4*>(&Y[(m0 + tm * 2 + i) * H_ + n]) = v;
    }
}

// ---------------- per-batch mean / rstd over TT*H values ----------
__global__ void stats_k(const float* __restrict__ X, float* __restrict__ stats) {
    __shared__ float sh[64];
    int b = blockIdx.x;
    const float* p = X + b * TT_ * H_;
    float s = 0.f, sq = 0.f;
    for (int i = threadIdx.x; i < TT_ * H_; i += blockDim.x) {
        float v = p[i];
        s += v; sq += v * v;
    }
#pragma unroll
    for (int o = 16; o; o >>= 1) {
        s += __shfl_xor_sync(0xffffffffu, s, o);
        sq += __shfl_xor_sync(0xffffffffu, sq, o);
    }
    int w = threadIdx.x >> 5, l = threadIdx.x & 31;
    if (l == 0) { sh[w] = s; sh[32 + w] = sq; }
    __syncthreads();
    if (threadIdx.x == 0) {
        int nw = blockDim.x >> 5;
        float ss = 0.f, ssq = 0.f;
        for (int i = 0; i < nw; i++) { ss += sh[i]; ssq += sh[32 + i]; }
        float inv = 1.0f / (float)(TT_ * H_);
        float mu = ss * inv;
        float var = ssq * inv - mu * mu;
        stats[b * 2] = mu;
        stats[b * 2 + 1] = rsqrtf(var + EPS_);
    }
}

// ---------------- apply GN1 into a fresh buffer ----------------
__global__ void gnapply_k(const float* __restrict__ x, const float* __restrict__ g,
                          const float* __restrict__ bb, const float* __restrict__ stats,
                          float* __restrict__ y) {
    int i = blockIdx.x * 256 + threadIdx.x;           // < B*TT*H = 262144
    int b = i >> 17;                                   // TT*H = 131072
    float mu = stats[b * 2], rs = stats[b * 2 + 1];
    int col = i & (H_ - 1);
    y[i] = (x[i] - mu) * rs * g[col] + bb[col];
}

// ---------------- fused logits ----------------
__global__ void logits_k(const float* __restrict__ tpart, const float* __restrict__ apart,
                         const float* __restrict__ w2, const float* __restrict__ b2,
                         float* __restrict__ L) {
    __shared__ __align__(16) float Ts[16][33];
    __shared__ __align__(16) float Am[64][33];
    __shared__ float ws[32];
    int b = blockIdx.z;
    int t0 = blockIdx.y * 16;
    int a0 = blockIdx.x * 64;
    int tid = threadIdx.x;
    int ty = tid >> 5;
    int tx = tid & 31;
    float acc[2][2] = {};
    const float* Tp = tpart + (b * TT_ + t0) * H_;
    const float* Ap = apart + (b * TA_ + a0) * H_;
    for (int h0 = 0; h0 < H_; h0 += 32) {
#pragma unroll
        for (int l = 0; l < 2; l++) {
            int idx = tid + l * 256;
            int r = idx >> 5, c = idx & 31;
            Ts[r][c] = Tp[r * H_ + h0 + c];
        }
#pragma unroll
        for (int l = 0; l < 8; l++) {
            int idx = tid + l * 256;
            int r = idx >> 5, c = idx & 31;
            Am[r][c] = Ap[r * H_ + h0 + c];
        }
        if (tid < 32) ws[tid] = w2[h0 + tid];
        __syncthreads();
#pragma unroll
        for (int hh = 0; hh < 32; hh++) {
            float w = ws[hh];
            float tv0 = Ts[ty][hh], tv1 = Ts[ty + 8][hh];
            float av0 = Am[tx][hh], av1 = Am[tx + 32][hh];
            acc[0][0] += fmaxf(tv0 + av0, 0.f) * w;
            acc[0][1] += fmaxf(tv0 + av1, 0.f) * w;
            acc[1][0] += fmaxf(tv1 + av0, 0.f) * w;
            acc[1][1] += fmaxf(tv1 + av1, 0.f) * w;
        }
        __syncthreads();
    }
    float bb = b2[0];
#pragma unroll
    for (int i = 0; i < 2; i++) {
        int t = t0 + ty + i * 8;
#pragma unroll
        for (int j = 0; j < 2; j++) {
            int a = a0 + tx + j * 32;
            float bias = -0.1f * fabsf((float)a - (float)t * 4.0f);
            L[(b * TT_ + t) * TA_ + a] = acc[i][j] + bb + bias;
        }
    }
}

// ---------------- softmax over TA=512 per (b,t) row ----------------
__global__ void softmax_k(const float* __restrict__ L, float* __restrict__ out) {
    __shared__ float wred[16];
    __shared__ float s_bcast;
    int row = blockIdx.x;
    int tid = threadIdx.x;
    float v = L[row * TA_ + tid];
    float m = v;
#pragma unroll
    for (int o = 16; o; o >>= 1) m = fmaxf(m, __shfl_xor_sync(0xffffffffu, m, o));
    if ((tid & 31) == 0) wred[tid >> 5] = m;
    __syncthreads();
    if (tid == 0) {
        float mm = wred[0];
        for (int i = 1; i < 16; i++) mm = fmaxf(mm, wred[i]);
        s_bcast = mm;
    }
    __syncthreads();
    float mx = s_bcast;
    float e = expf(v - mx);
    float s = e;
#pragma unroll
    for (int o = 16; o; o >>= 1) s += __shfl_xor_sync(0xffffffffu, s, o);
    if ((tid & 31) == 0) wred[tid >> 5] = s;
    __syncthreads();
    if (tid == 0) {
        float ss = 0.f;
        for (int i = 0; i < 16; i++) ss += wred[i];
        s_bcast = ss;
    }
    __syncthreads();
    out[row * TA_ + tid] = e / s_bcast;
}

// ---------------- conv3 (H->1,k=1) on gn2(x2) + softplus ----------------
__global__ void dur_k(const float* __restrict__ X2, const float* __restrict__ w3,
                      const float* __restrict__ b3,
                      const float* __restrict__ gng, const float* __restrict__ gnb,
                      const float* __restrict__ stats, float* __restrict__ out) {
    __shared__ float wred[8];
    int bt = blockIdx.x;
    int b = bt / TT_;
    float mu = stats[b * 2], rstd = stats[b * 2 + 1];
    const float* x = X2 + bt * H_;
    int tid = threadIdx.x;
    float s = 0.f;
    for (int i = tid; i < H_; i += 256) {
        float v = (x[i] - mu) * rstd * gng[i] + gnb[i];
        s += v * w3[i];
    }
#pragma unroll
    for (int o = 16; o; o >>= 1) s += __shfl_xor_sync(0xffffffffu, s, o);
    if ((tid & 31) == 0) wred[tid >> 5] = s;
    __syncthreads();
    if (tid == 0) {
        float ss = 0.f;
        for (int i = 0; i < 8; i++) ss += wred[i];
        float z = ss + b3[0];
        out[bt] = fmaxf(z, 0.f) + log1pf(expf(-fabsf(z)));
    }
}

// ---------------- launch ----------------
extern "C" void kernel_launch(void* const* d_in, const int* in_sizes, int n_in,
                              void* d_out, int out_size) {
    (void)in_sizes; (void)n_in; (void)out_size;
    const float* text  = (const float*)d_in[0];
    const float* audio = (const float*)d_in[1];
    const float* a_w1  = (const float*)d_in[2];
    const float* a_b1  = (const float*)d_in[3];
    const float* a_w2  = (const float*)d_in[4];
    const float* a_b2  = (const float*)d_in[5];
    const float* d_w1  = (const float*)d_in[6];
    const float* d_b1  = (const float*)d_in[7];
    const float* gn1g  = (const float*)d_in[8];
    const float* gn1b  = (const float*)d_in[9];
    const float* d_w2  = (const float*)d_in[10];
    const float* d_b2  = (const float*)d_in[11];
    const float* gn2g  = (const float*)d_in[12];
    const float* gn2b  = (const float*)d_in[13];
    const float* d_w3  = (const float*)d_in[14];
    const float* d_b3  = (const float*)d_in[15];
    float* out = (float*)d_out;

    float *tpart, *apart, *x1, *xn, *x2, *logits, *stats, *w1t, *w2t;
    cudaGetSymbolAddress((void**)&tpart,  g_tpart);
    cudaGetSymbolAddress((void**)&apart,  g_apart);
    cudaGetSymbolAddress((void**)&x1,     g_x1);
    cudaGetSymbolAddress((void**)&xn,     g_xn);
    cudaGetSymbolAddress((void**)&x2,     g_x2);
    cudaGetSymbolAddress((void**)&logits, g_logits);
    cudaGetSymbolAddress((void**)&stats,  g_stats);
    cudaGetSymbolAddress((void**)&w1t,    g_w1t);
    cudaGetSymbolAddress((void**)&w2t,    g_w2t);

    // ---- weight transposes ----
    dim3 tb(32, 8);
    dim3 tg(H_ / 32, H_ / 32);
    transpose_w_k<<<tg, tb>>>(d_w1, w1t);
    transpose_w_k<<<tg, tb>>>(d_w2, w2t);

    // ---- alignment path ----
    gemm32_k<true, false><<<dim3(H_ / 64, (B_ * TT_) / 32), 256>>>(
        text, a_w1, a_b1, tpart, B_ * TT_, H_, H_);
    gemm64_k<false, false><<<dim3(H_ / 64, (B_ * TA_) / 64), 256>>>(
        audio, a_w1 + H_ * H_, nullptr, apart, B_ * TA_, H_, H_);
    logits_k<<<dim3(TA_ / 64, TT_ / 16, B_), 256>>>(tpart, apart, a_w2, a_b2, logits);
    softmax_k<<<B_ * TT_, TA_>>>(logits, out);

    // ---- duration path ----
    conv3_k<<<dim3(H_ / 64, (B_ * TT_) / 32), 256>>>(text, w1t, d_b1, x1);
    stats_k<<<B_, 512>>>(x1, stats);
    gnapply_k<<<(B_ * TT_ * H_) / 256, 256>>>(x1, gn1g, gn1b, stats, xn);
    conv3_k<<<dim3(H_ / 64, (B_ * TT_) / 32), 256>>>(xn, w2t, d_b2, x2);
    stats_k<<<B_, 512>>>(x2, stats + 4);
    dur_k<<<B_ * TT_, 256>>>(x2, d_w3, d_b3, gn2g, gn2b, stats + 4,
                             out + B_ * TT_ * TA_);
}

// round 3
// speedup vs baseline: 1.2589x; 1.1310x over previous
#include <cuda_runtime.h>
#include <math.h>

#define B_   2
#define TT_  128
#define TA_  512
#define H_   1024
#define EPS_ 1e-5f

typedef unsigned long long u64;

// ---------------- packed fp32x2 helpers (sm_103a FFMA2) ----------------
__device__ __forceinline__ u64 pack_dup(float a) {
    u64 r; asm("mov.b64 %0, {%1,%1};" : "=l"(r) : "f"(a)); return r;
}
__device__ __forceinline__ float2 unpack2(u64 v) {
    float2 f; asm("mov.b64 {%0,%1}, %2;" : "=f"(f.x), "=f"(f.y) : "l"(v)); return f;
}
__device__ __forceinline__ void ffma2(u64& acc, u64 a, u64 b) {
    asm("fma.rn.f32x2 %0, %1, %2, %0;" : "+l"(acc) : "l"(a), "l"(b));
}

// ---------------- scratch ----------------
__device__ float g_tpart[B_ * TT_ * H_];
__device__ float g_apart[B_ * TA_ * H_];
__device__ float g_x1[B_ * TT_ * H_];
__device__ float g_xn[B_ * TT_ * H_];
__device__ float g_x2[B_ * TT_ * H_];
__device__ float g_logits[B_ * TT_ * TA_];
__device__ float g_stats[8];
__device__ float g_w1t[3 * H_ * H_];
__device__ float g_w2t[3 * H_ * H_];

// ---------------- weight transpose [O][I][3] -> [3][I][O] ----------------
__global__ void transpose_w_k(const float* __restrict__ W, float* __restrict__ Wt) {
    __shared__ float s[32][97];
    int o0 = blockIdx.x * 32;
    int i0 = blockIdx.y * 32;
    int tx = threadIdx.x, ty = threadIdx.y;
    for (int rr = ty; rr < 32; rr += 8)
        for (int cc = tx; cc < 96; cc += 32)
            s[rr][cc] = W[(o0 + rr) * 3 * H_ + i0 * 3 + cc];
    __syncthreads();
    for (int il = ty; il < 32; il += 8) {
#pragma unroll
        for (int k = 0; k < 3; k++)
            Wt[k * H_ * H_ + (i0 + il) * H_ + o0 + tx] = s[tx][il * 3 + k];
    }
}

// ============ double-buffered 64x64 GEMM, TK=16, 256 thr, 4x4, FFMA2 =======
// C[M,N] = A[M,K] @ Bw[K,N] (+bias). M%64==0, N%64==0, K%16==0.
template <bool BIAS>
__global__ void gemm64_k(const float* __restrict__ A, const float* __restrict__ Bw,
                         const float* __restrict__ bias, float* __restrict__ C,
                         int M, int N, int K) {
    __shared__ __align__(16) float As[2][16][68];
    __shared__ __align__(16) float Bs[2][16][64];
    int tid = threadIdx.x;
    int m0 = blockIdx.y * 64;
    int n0 = blockIdx.x * 64;
    int tm = tid >> 4, tn = tid & 15;
    int ar = tid >> 2, ac = (tid & 3) * 4;
    int br = tid >> 4, bc = (tid & 15) * 4;

    const float* Aptr = A + (m0 + ar) * K + ac;
    const float* Bptr = Bw + br * N + n0 + bc;

    // prologue: load tile 0 into buffer 0
    float4 a4 = *reinterpret_cast<const float4*>(Aptr);
    float4 b4 = *reinterpret_cast<const float4*>(Bptr);
    As[0][ac + 0][ar] = a4.x; As[0][ac + 1][ar] = a4.y;
    As[0][ac + 2][ar] = a4.z; As[0][ac + 3][ar] = a4.w;
    *reinterpret_cast<float4*>(&Bs[0][br][bc]) = b4;
    __syncthreads();

    u64 acc[4][2] = {};
    int buf = 0;
    for (int k0 = 0; k0 < K; k0 += 16) {
        bool more = (k0 + 16) < K;
        float4 a4n, b4n;
        if (more) {
            a4n = *reinterpret_cast<const float4*>(Aptr + k0 + 16);
            b4n = *reinterpret_cast<const float4*>(Bptr + (k0 + 16) * N);
        }
#pragma unroll
        for (int kk = 0; kk < 16; kk++) {
            float4 av = *reinterpret_cast<const float4*>(&As[buf][kk][tm * 4]);
            ulonglong2 bv = *reinterpret_cast<const ulonglong2*>(&Bs[buf][kk][tn * 4]);
            u64 a0 = pack_dup(av.x), a1 = pack_dup(av.y);
            u64 a2 = pack_dup(av.z), a3 = pack_dup(av.w);
            ffma2(acc[0][0], a0, bv.x); ffma2(acc[0][1], a0, bv.y);
            ffma2(acc[1][0], a1, bv.x); ffma2(acc[1][1], a1, bv.y);
            ffma2(acc[2][0], a2, bv.x); ffma2(acc[2][1], a2, bv.y);
            ffma2(acc[3][0], a3, bv.x); ffma2(acc[3][1], a3, bv.y);
        }
        if (more) {
            int nb = buf ^ 1;
            As[nb][ac + 0][ar] = a4n.x; As[nb][ac + 1][ar] = a4n.y;
            As[nb][ac + 2][ar] = a4n.z; As[nb][ac + 3][ar] = a4n.w;
            *reinterpret_cast<float4*>(&Bs[nb][br][bc]) = b4n;
            __syncthreads();
            buf = nb;
        }
    }
    int n = n0 + tn * 4;
    float4 bv = BIAS ? *reinterpret_cast<const float4*>(&bias[n])
                     : make_float4(0.f, 0.f, 0.f, 0.f);
#pragma unroll
    for (int i = 0; i < 4; i++) {
        float2 p0 = unpack2(acc[i][0]);
        float2 p1 = unpack2(acc[i][1]);
        float4 v = make_float4(p0.x + bv.x, p0.y + bv.y, p1.x + bv.z, p1.y + bv.w);
        *reinterpret_cast<float4*>(&C[(m0 + tm * 4 + i) * N + n]) = v;
    }
}

// ============ conv1d(H,H,3) as one flattened K=3*H GEMM, double-buffered ===
// Y[bt,o] = relu(bias[o] + sum over flattened (k,i): X[bt+k-1,i]*Wt[k*H+i][o])
__global__ void conv64_k(const float* __restrict__ X, const float* __restrict__ Wt,
                         const float* __restrict__ bias, float* __restrict__ Y) {
    __shared__ __align__(16) float As[2][16][68];
    __shared__ __align__(16) float Bs[2][16][64];
    const int KF = 3 * H_;
    int tid = threadIdx.x;
    int m0 = blockIdx.y * 64;
    int n0 = blockIdx.x * 64;
    int tm = tid >> 4, tn = tid & 15;
    int ar = tid >> 2, ac = (tid & 3) * 4;
    int br = tid >> 4, bc = (tid & 15) * 4;

    int bt = m0 + ar;
    int b = bt >> 7;        // / TT_
    int tloc = bt & 127;
    const float* Xb = X + b * TT_ * H_;
    const float* Bptr = Wt + br * H_ + n0 + bc;

    // A fetch helper values computed inline per tile:
    //   kg = k0 global; ktap = kg >> 10; koff = kg & 1023; tp = tloc + ktap - 1
    float4 a4, b4;
    {
        int ktap = 0, koff = ac;
        int tp = tloc + ktap - 1;
        a4 = make_float4(0.f, 0.f, 0.f, 0.f);
        if (tp >= 0 && tp < TT_)
            a4 = *reinterpret_cast<const float4*>(&Xb[tp * H_ + koff]);
        b4 = *reinterpret_cast<const float4*>(Bptr);
    }
    As[0][ac + 0][ar] = a4.x; As[0][ac + 1][ar] = a4.y;
    As[0][ac + 2][ar] = a4.z; As[0][ac + 3][ar] = a4.w;
    *reinterpret_cast<float4*>(&Bs[0][br][bc]) = b4;
    __syncthreads();

    u64 acc[4][2] = {};
    int buf = 0;
    for (int k0 = 0; k0 < KF; k0 += 16) {
        bool more = (k0 + 16) < KF;
        float4 a4n, b4n;
        if (more) {
            int kg = k0 + 16;
            int ktap = kg >> 10;
            int koff = (kg & 1023) + ac;
            int tp = tloc + ktap - 1;
            a4n = make_float4(0.f, 0.f, 0.f, 0.f);
            if (tp >= 0 && tp < TT_)
                a4n = *reinterpret_cast<const float4*>(&Xb[tp * H_ + koff]);
            b4n = *reinterpret_cast<const float4*>(Bptr + kg * H_);
        }
#pragma unroll
        for (int kk = 0; kk < 16; kk++) {
            float4 av = *reinterpret_cast<const float4*>(&As[buf][kk][tm * 4]);
            ulonglong2 bv = *reinterpret_cast<const ulonglong2*>(&Bs[buf][kk][tn * 4]);
            u64 a0 = pack_dup(av.x), a1 = pack_dup(av.y);
            u64 a2 = pack_dup(av.z), a3 = pack_dup(av.w);
            ffma2(acc[0][0], a0, bv.x); ffma2(acc[0][1], a0, bv.y);
            ffma2(acc[1][0], a1, bv.x); ffma2(acc[1][1], a1, bv.y);
            ffma2(acc[2][0], a2, bv.x); ffma2(acc[2][1], a2, bv.y);
            ffma2(acc[3][0], a3, bv.x); ffma2(acc[3][1], a3, bv.y);
        }
        if (more) {
            int nb = buf ^ 1;
            As[nb][ac + 0][ar] = a4n.x; As[nb][ac + 1][ar] = a4n.y;
            As[nb][ac + 2][ar] = a4n.z; As[nb][ac + 3][ar] = a4n.w;
            *reinterpret_cast<float4*>(&Bs[nb][br][bc]) = b4n;
            __syncthreads();
            buf = nb;
        }
    }
    int n = n0 + tn * 4;
    float4 bvb = *reinterpret_cast<const float4*>(&bias[n]);
#pragma unroll
    for (int i = 0; i < 4; i++) {
        float2 p0 = unpack2(acc[i][0]);
        float2 p1 = unpack2(acc[i][1]);
        float4 v = make_float4(fmaxf(p0.x + bvb.x, 0.f), fmaxf(p0.y + bvb.y, 0.f),
                               fmaxf(p1.x + bvb.z, 0.f), fmaxf(p1.y + bvb.w, 0.f));
        *reinterpret_cast<float4*>(&Y[(m0 + tm * 4 + i) * H_ + n]) = v;
    }
}

// ---------------- per-batch mean / rstd over TT*H values ----------
__global__ void stats_k(const float* __restrict__ X, float* __restrict__ stats) {
    __shared__ float sh[64];
    int b = blockIdx.x;
    const float* p = X + b * TT_ * H_;
    float s = 0.f, sq = 0.f;
    for (int i = threadIdx.x; i < TT_ * H_; i += blockDim.x) {
        float v = p[i];
        s += v; sq += v * v;
    }
#pragma unroll
    for (int o = 16; o; o >>= 1) {
        s += __shfl_xor_sync(0xffffffffu, s, o);
        sq += __shfl_xor_sync(0xffffffffu, sq, o);
    }
    int w = threadIdx.x >> 5, l = threadIdx.x & 31;
    if (l == 0) { sh[w] = s; sh[32 + w] = sq; }
    __syncthreads();
    if (threadIdx.x == 0) {
        int nw = blockDim.x >> 5;
        float ss = 0.f, ssq = 0.f;
        for (int i = 0; i < nw; i++) { ss += sh[i]; ssq += sh[32 + i]; }
        float inv = 1.0f / (float)(TT_ * H_);
        float mu = ss * inv;
        float var = ssq * inv - mu * mu;
        stats[b * 2] = mu;
        stats[b * 2 + 1] = rsqrtf(var + EPS_);
    }
}

// ---------------- apply GN1 into a fresh buffer ----------------
__global__ void gnapply_k(const float* __restrict__ x, const float* __restrict__ g,
                          const float* __restrict__ bb, const float* __restrict__ stats,
                          float* __restrict__ y) {
    int i = blockIdx.x * 256 + threadIdx.x;
    int b = i >> 17;
    float mu = stats[b * 2], rs = stats[b * 2 + 1];
    int col = i & (H_ - 1);
    y[i] = (x[i] - mu) * rs * g[col] + bb[col];
}

// ---------------- fused logits ----------------
__global__ void logits_k(const float* __restrict__ tpart, const float* __restrict__ apart,
                         const float* __restrict__ w2, const float* __restrict__ b2,
                         float* __restrict__ L) {
    __shared__ __align__(16) float Ts[16][33];
    __shared__ __align__(16) float Am[64][33];
    __shared__ float ws[32];
    int b = blockIdx.z;
    int t0 = blockIdx.y * 16;
    int a0 = blockIdx.x * 64;
    int tid = threadIdx.x;
    int ty = tid >> 5;
    int tx = tid & 31;
    float acc[2][2] = {};
    const float* Tp = tpart + (b * TT_ + t0) * H_;
    const float* Ap = apart + (b * TA_ + a0) * H_;
    for (int h0 = 0; h0 < H_; h0 += 32) {
#pragma unroll
        for (int l = 0; l < 2; l++) {
            int idx = tid + l * 256;
            int r = idx >> 5, c = idx & 31;
            Ts[r][c] = Tp[r * H_ + h0 + c];
        }
#pragma unroll
        for (int l = 0; l < 8; l++) {
            int idx = tid + l * 256;
            int r = idx >> 5, c = idx & 31;
            Am[r][c] = Ap[r * H_ + h0 + c];
        }
        if (tid < 32) ws[tid] = w2[h0 + tid];
        __syncthreads();
#pragma unroll
        for (int hh = 0; hh < 32; hh++) {
            float w = ws[hh];
            float tv0 = Ts[ty][hh], tv1 = Ts[ty + 8][hh];
            float av0 = Am[tx][hh], av1 = Am[tx + 32][hh];
            acc[0][0] += fmaxf(tv0 + av0, 0.f) * w;
            acc[0][1] += fmaxf(tv0 + av1, 0.f) * w;
            acc[1][0] += fmaxf(tv1 + av0, 0.f) * w;
            acc[1][1] += fmaxf(tv1 + av1, 0.f) * w;
        }
        __syncthreads();
    }
    float bb = b2[0];
#pragma unroll
    for (int i = 0; i < 2; i++) {
        int t = t0 + ty + i * 8;
#pragma unroll
        for (int j = 0; j < 2; j++) {
            int a = a0 + tx + j * 32;
            float bias = -0.1f * fabsf((float)a - (float)t * 4.0f);
            L[(b * TT_ + t) * TA_ + a] = acc[i][j] + bb + bias;
        }
    }
}

// ---------------- softmax over TA=512 per (b,t) row ----------------
__global__ void softmax_k(const float* __restrict__ L, float* __restrict__ out) {
    __shared__ float wred[16];
    __shared__ float s_bcast;
    int row = blockIdx.x;
    int tid = threadIdx.x;
    float v = L[row * TA_ + tid];
    float m = v;
#pragma unroll
    for (int o = 16; o; o >>= 1) m = fmaxf(m, __shfl_xor_sync(0xffffffffu, m, o));
    if ((tid & 31) == 0) wred[tid >> 5] = m;
    __syncthreads();
    if (tid == 0) {
        float mm = wred[0];
        for (int i = 1; i < 16; i++) mm = fmaxf(mm, wred[i]);
        s_bcast = mm;
    }
    __syncthreads();
    float mx = s_bcast;
    float e = expf(v - mx);
    float s = e;
#pragma unroll
    for (int o = 16; o; o >>= 1) s += __shfl_xor_sync(0xffffffffu, s, o);
    if ((tid & 31) == 0) wred[tid >> 5] = s;
    __syncthreads();
    if (tid == 0) {
        float ss = 0.f;
        for (int i = 0; i < 16; i++) ss += wred[i];
        s_bcast = ss;
    }
    __syncthreads();
    out[row * TA_ + tid] = e / s_bcast;
}

// ---------------- conv3 (H->1,k=1) on gn2(x2) + softplus ----------------
__global__ void dur_k(const float* __restrict__ X2, const float* __restrict__ w3,
                      const float* __restrict__ b3,
                      const float* __restrict__ gng, const float* __restrict__ gnb,
                      const float* __restrict__ stats, float* __restrict__ out) {
    __shared__ float wred[8];
    int bt = blockIdx.x;
    int b = bt / TT_;
    float mu = stats[b * 2], rstd = stats[b * 2 + 1];
    const float* x = X2 + bt * H_;
    int tid = threadIdx.x;
    float s = 0.f;
    for (int i = tid; i < H_; i += 256) {
        float v = (x[i] - mu) * rstd * gng[i] + gnb[i];
        s += v * w3[i];
    }
#pragma unroll
    for (int o = 16; o; o >>= 1) s += __shfl_xor_sync(0xffffffffu, s, o);
    if ((tid & 31) == 0) wred[tid >> 5] = s;
    __syncthreads();
    if (tid == 0) {
        float ss = 0.f;
        for (int i = 0; i < 8; i++) ss += wred[i];
        float z = ss + b3[0];
        out[bt] = fmaxf(z, 0.f) + log1pf(expf(-fabsf(z)));
    }
}

// ---------------- launch (fork/join: duration path on side stream) --------
extern "C" void kernel_launch(void* const* d_in, const int* in_sizes, int n_in,
                              void* d_out, int out_size) {
    (void)in_sizes; (void)n_in; (void)out_size;
    const float* text  = (const float*)d_in[0];
    const float* audio = (const float*)d_in[1];
    const float* a_w1  = (const float*)d_in[2];
    const float* a_b1  = (const float*)d_in[3];
    const float* a_w2  = (const float*)d_in[4];
    const float* a_b2  = (const float*)d_in[5];
    const float* d_w1  = (const float*)d_in[6];
    const float* d_b1  = (const float*)d_in[7];
    const float* gn1g  = (const float*)d_in[8];
    const float* gn1b  = (const float*)d_in[9];
    const float* d_w2  = (const float*)d_in[10];
    const float* d_b2  = (const float*)d_in[11];
    const float* gn2g  = (const float*)d_in[12];
    const float* gn2b  = (const float*)d_in[13];
    const float* d_w3  = (const float*)d_in[14];
    const float* d_b3  = (const float*)d_in[15];
    float* out = (float*)d_out;

    float *tpart, *apart, *x1, *xn, *x2, *logits, *stats, *w1t, *w2t;
    cudaGetSymbolAddress((void**)&tpart,  g_tpart);
    cudaGetSymbolAddress((void**)&apart,  g_apart);
    cudaGetSymbolAddress((void**)&x1,     g_x1);
    cudaGetSymbolAddress((void**)&xn,     g_xn);
    cudaGetSymbolAddress((void**)&x2,     g_x2);
    cudaGetSymbolAddress((void**)&logits, g_logits);
    cudaGetSymbolAddress((void**)&stats,  g_stats);
    cudaGetSymbolAddress((void**)&w1t,    g_w1t);
    cudaGetSymbolAddress((void**)&w2t,    g_w2t);

    // fork a side stream into the capture (duration path)
    cudaStream_t sDur;
    cudaStreamCreateWithFlags(&sDur, cudaStreamNonBlocking);
    cudaEvent_t evFork, evJoin;
    cudaEventCreateWithFlags(&evFork, cudaEventDisableTiming);
    cudaEventCreateWithFlags(&evJoin, cudaEventDisableTiming);
    cudaEventRecord(evFork, 0);
    cudaStreamWaitEvent(sDur, evFork, 0);

    // ---- duration path (side stream) ----
    dim3 tb(32, 8);
    dim3 tg(H_ / 32, H_ / 32);
    transpose_w_k<<<tg, tb, 0, sDur>>>(d_w1, w1t);
    transpose_w_k<<<tg, tb, 0, sDur>>>(d_w2, w2t);
    conv64_k<<<dim3(H_ / 64, (B_ * TT_) / 64), 256, 0, sDur>>>(text, w1t, d_b1, x1);
    stats_k<<<B_, 512, 0, sDur>>>(x1, stats);
    gnapply_k<<<(B_ * TT_ * H_) / 256, 256, 0, sDur>>>(x1, gn1g, gn1b, stats, xn);
    conv64_k<<<dim3(H_ / 64, (B_ * TT_) / 64), 256, 0, sDur>>>(xn, w2t, d_b2, x2);
    stats_k<<<B_, 512, 0, sDur>>>(x2, stats + 4);
    dur_k<<<B_ * TT_, 256, 0, sDur>>>(x2, d_w3, d_b3, gn2g, gn2b, stats + 4,
                                      out + B_ * TT_ * TA_);
    cudaEventRecord(evJoin, sDur);

    // ---- alignment path (main stream) ----
    gemm64_k<true><<<dim3(H_ / 64, (B_ * TT_) / 64), 256>>>(
        text, a_w1, a_b1, tpart, B_ * TT_, H_, H_);
    gemm64_k<false><<<dim3(H_ / 64, (B_ * TA_) / 64), 256>>>(
        audio, a_w1 + H_ * H_, nullptr, apart, B_ * TA_, H_, H_);
    logits_k<<<dim3(TA_ / 64, TT_ / 16, B_), 256>>>(tpart, apart, a_w2, a_b2, logits);
    softmax_k<<<B_ * TT_, TA_>>>(logits, out);

    // join
    cudaStreamWaitEvent(0, evJoin, 0);
}

// round 5
// speedup vs baseline: 1.5286x; 1.2142x over previous
#include <cuda_runtime.h>
#include <math.h>

#define B_   2
#define TT_  128
#define TA_  512
#define H_   1024
#define EPS_ 1e-5f
#define HSPLIT 8
#define HCHUNK (H_ / HSPLIT)   // 128

typedef unsigned long long u64;

// ---------------- packed fp32x2 helpers (sm_103a) ----------------
__device__ __forceinline__ u64 pack_dup(float a) {
    u64 r; asm("mov.b64 %0, {%1,%1};" : "=l"(r) : "f"(a)); return r;
}
__device__ __forceinline__ float2 unpack2(u64 v) {
    float2 f; asm("mov.b64 {%0,%1}, %2;" : "=f"(f.x), "=f"(f.y) : "l"(v)); return f;
}
__device__ __forceinline__ void ffma2(u64& acc, u64 a, u64 b) {
    asm("fma.rn.f32x2 %0, %1, %2, %0;" : "+l"(acc) : "l"(a), "l"(b));
}
__device__ __forceinline__ u64 fadd2(u64 a, u64 b) {
    u64 r; asm("add.rn.f32x2 %0, %1, %2;" : "=l"(r) : "l"(a), "l"(b)); return r;
}
// relu on a packed pair: unpack (register aliasing), 2x FMNMX (alu pipe), repack
__device__ __forceinline__ u64 relu2(u64 v) {
    float2 f = unpack2(v);
    f.x = fmaxf(f.x, 0.f);
    f.y = fmaxf(f.y, 0.f);
    u64 r; asm("mov.b64 %0, {%1,%2};" : "=l"(r) : "f"(f.x), "f"(f.y));
    return r;
}

// ---------------- scratch ----------------
__device__ float g_tpart[B_ * TT_ * H_];
__device__ float g_apart[B_ * TA_ * H_];
__device__ float g_x1[B_ * TT_ * H_];
__device__ float g_xn[B_ * TT_ * H_];
__device__ float g_x2[B_ * TT_ * H_];
__device__ float g_lp[HSPLIT * B_ * TT_ * TA_];   // logits partials
__device__ float g_stats[8];                       // mu,rstd (gn1 b0,b1, gn2 b0,b1)
__device__ float2 g_ps[2 * B_ * 32];               // conv partial sums [phase][b][slot]
__device__ float g_w1t[3 * H_ * H_];
__device__ float g_w2t[3 * H_ * H_];

// ---------------- weight transpose [O][I][3] -> [3][I][O] ----------------
__global__ void transpose_w_k(const float* __restrict__ W, float* __restrict__ Wt) {
    __shared__ float s[32][97];
    int o0 = blockIdx.x * 32;
    int i0 = blockIdx.y * 32;
    int tx = threadIdx.x, ty = threadIdx.y;
    for (int rr = ty; rr < 32; rr += 8)
        for (int cc = tx; cc < 96; cc += 32)
            s[rr][cc] = W[(o0 + rr) * 3 * H_ + i0 * 3 + cc];
    __syncthreads();
    for (int il = ty; il < 32; il += 8) {
#pragma unroll
        for (int k = 0; k < 3; k++)
            Wt[k * H_ * H_ + (i0 + il) * H_ + o0 + tx] = s[tx][il * 3 + k];
    }
}

// ============ double-buffered 64x64 GEMM, TK=16, 256 thr, 4x4, FFMA2 =======
template <bool BIAS>
__global__ void gemm64_k(const float* __restrict__ A, const float* __restrict__ Bw,
                         const float* __restrict__ bias, float* __restrict__ C,
                         int M, int N, int K) {
    __shared__ __align__(16) float As[2][16][68];
    __shared__ __align__(16) float Bs[2][16][64];
    int tid = threadIdx.x;
    int m0 = blockIdx.y * 64;
    int n0 = blockIdx.x * 64;
    int tm = tid >> 4, tn = tid & 15;
    int ar = tid >> 2, ac = (tid & 3) * 4;
    int br = tid >> 4, bc = (tid & 15) * 4;

    const float* Aptr = A + (m0 + ar) * K + ac;
    const float* Bptr = Bw + br * N + n0 + bc;

    float4 a4 = *reinterpret_cast<const float4*>(Aptr);
    float4 b4 = *reinterpret_cast<const float4*>(Bptr);
    As[0][ac + 0][ar] = a4.x; As[0][ac + 1][ar] = a4.y;
    As[0][ac + 2][ar] = a4.z; As[0][ac + 3][ar] = a4.w;
    *reinterpret_cast<float4*>(&Bs[0][br][bc]) = b4;
    __syncthreads();

    u64 acc[4][2] = {};
    int buf = 0;
    for (int k0 = 0; k0 < K; k0 += 16) {
        bool more = (k0 + 16) < K;
        float4 a4n, b4n;
        if (more) {
            a4n = *reinterpret_cast<const float4*>(Aptr + k0 + 16);
            b4n = *reinterpret_cast<const float4*>(Bptr + (k0 + 16) * N);
        }
#pragma unroll
        for (int kk = 0; kk < 16; kk++) {
            float4 av = *reinterpret_cast<const float4*>(&As[buf][kk][tm * 4]);
            ulonglong2 bv = *reinterpret_cast<const ulonglong2*>(&Bs[buf][kk][tn * 4]);
            u64 a0 = pack_dup(av.x), a1 = pack_dup(av.y);
            u64 a2 = pack_dup(av.z), a3 = pack_dup(av.w);
            ffma2(acc[0][0], a0, bv.x); ffma2(acc[0][1], a0, bv.y);
            ffma2(acc[1][0], a1, bv.x); ffma2(acc[1][1], a1, bv.y);
            ffma2(acc[2][0], a2, bv.x); ffma2(acc[2][1], a2, bv.y);
            ffma2(acc[3][0], a3, bv.x); ffma2(acc[3][1], a3, bv.y);
        }
        if (more) {
            int nb = buf ^ 1;
            As[nb][ac + 0][ar] = a4n.x; As[nb][ac + 1][ar] = a4n.y;
            As[nb][ac + 2][ar] = a4n.z; As[nb][ac + 3][ar] = a4n.w;
            *reinterpret_cast<float4*>(&Bs[nb][br][bc]) = b4n;
            __syncthreads();
            buf = nb;
        }
    }
    int n = n0 + tn * 4;
    float4 bv = BIAS ? *reinterpret_cast<const float4*>(&bias[n])
                     : make_float4(0.f, 0.f, 0.f, 0.f);
#pragma unroll
    for (int i = 0; i < 4; i++) {
        float2 p0 = unpack2(acc[i][0]);
        float2 p1 = unpack2(acc[i][1]);
        float4 v = make_float4(p0.x + bv.x, p0.y + bv.y, p1.x + bv.z, p1.y + bv.w);
        *reinterpret_cast<float4*>(&C[(m0 + tm * 4 + i) * N + n]) = v;
    }
}

// ============ conv1d(H,H,3) flattened K=3H GEMM + stats partials ===========
__global__ void conv64_k(const float* __restrict__ X, const float* __restrict__ Wt,
                         const float* __restrict__ bias, float* __restrict__ Y,
                         float2* __restrict__ ps) {
    __shared__ __align__(16) float As[2][16][68];
    __shared__ __align__(16) float Bs[2][16][64];
    __shared__ float2 red[8];
    const int KF = 3 * H_;
    int tid = threadIdx.x;
    int m0 = blockIdx.y * 64;
    int n0 = blockIdx.x * 64;
    int tm = tid >> 4, tn = tid & 15;
    int ar = tid >> 2, ac = (tid & 3) * 4;
    int br = tid >> 4, bc = (tid & 15) * 4;

    int bt = m0 + ar;
    int b = bt >> 7;
    int tloc = bt & 127;
    const float* Xb = X + b * TT_ * H_;
    const float* Bptr = Wt + br * H_ + n0 + bc;

    float4 a4, b4;
    {
        int tp = tloc - 1;
        a4 = make_float4(0.f, 0.f, 0.f, 0.f);
        if (tp >= 0) a4 = *reinterpret_cast<const float4*>(&Xb[tp * H_ + ac]);
        b4 = *reinterpret_cast<const float4*>(Bptr);
    }
    As[0][ac + 0][ar] = a4.x; As[0][ac + 1][ar] = a4.y;
    As[0][ac + 2][ar] = a4.z; As[0][ac + 3][ar] = a4.w;
    *reinterpret_cast<float4*>(&Bs[0][br][bc]) = b4;
    __syncthreads();

    u64 acc[4][2] = {};
    int buf = 0;
    for (int k0 = 0; k0 < KF; k0 += 16) {
        bool more = (k0 + 16) < KF;
        float4 a4n, b4n;
        if (more) {
            int kg = k0 + 16;
            int ktap = kg >> 10;
            int koff = (kg & 1023) + ac;
            int tp = tloc + ktap - 1;
            a4n = make_float4(0.f, 0.f, 0.f, 0.f);
            if (tp >= 0 && tp < TT_)
                a4n = *reinterpret_cast<const float4*>(&Xb[tp * H_ + koff]);
            b4n = *reinterpret_cast<const float4*>(Bptr + kg * H_);
        }
#pragma unroll
        for (int kk = 0; kk < 16; kk++) {
            float4 av = *reinterpret_cast<const float4*>(&As[buf][kk][tm * 4]);
            ulonglong2 bv = *reinterpret_cast<const ulonglong2*>(&Bs[buf][kk][tn * 4]);
            u64 a0 = pack_dup(av.x), a1 = pack_dup(av.y);
            u64 a2 = pack_dup(av.z), a3 = pack_dup(av.w);
            ffma2(acc[0][0], a0, bv.x); ffma2(acc[0][1], a0, bv.y);
            ffma2(acc[1][0], a1, bv.x); ffma2(acc[1][1], a1, bv.y);
            ffma2(acc[2][0], a2, bv.x); ffma2(acc[2][1], a2, bv.y);
            ffma2(acc[3][0], a3, bv.x); ffma2(acc[3][1], a3, bv.y);
        }
        if (more) {
            int nb = buf ^ 1;
            As[nb][ac + 0][ar] = a4n.x; As[nb][ac + 1][ar] = a4n.y;
            As[nb][ac + 2][ar] = a4n.z; As[nb][ac + 3][ar] = a4n.w;
            *reinterpret_cast<float4*>(&Bs[nb][br][bc]) = b4n;
            __syncthreads();
            buf = nb;
        }
    }
    int n = n0 + tn * 4;
    float4 bvb = *reinterpret_cast<const float4*>(&bias[n]);
    float s = 0.f, sq = 0.f;
#pragma unroll
    for (int i = 0; i < 4; i++) {
        float2 p0 = unpack2(acc[i][0]);
        float2 p1 = unpack2(acc[i][1]);
        float4 v = make_float4(fmaxf(p0.x + bvb.x, 0.f), fmaxf(p0.y + bvb.y, 0.f),
                               fmaxf(p1.x + bvb.z, 0.f), fmaxf(p1.y + bvb.w, 0.f));
        s += v.x + v.y + v.z + v.w;
        sq += v.x * v.x + v.y * v.y + v.z * v.z + v.w * v.w;
        *reinterpret_cast<float4*>(&Y[(m0 + tm * 4 + i) * H_ + n]) = v;
    }
    // block-reduce (sum, sumsq) -> partial slot
#pragma unroll
    for (int o = 16; o; o >>= 1) {
        s += __shfl_xor_sync(0xffffffffu, s, o);
        sq += __shfl_xor_sync(0xffffffffu, sq, o);
    }
    if ((tid & 31) == 0) red[tid >> 5] = make_float2(s, sq);
    __syncthreads();
    if (tid == 0) {
        float2 t = make_float2(0.f, 0.f);
        for (int i = 0; i < 8; i++) { t.x += red[i].x; t.y += red[i].y; }
        int bb = blockIdx.y >> 1;
        int slot = blockIdx.x * 2 + (blockIdx.y & 1);
        ps[bb * 32 + slot] = t;
    }
}

// ---------------- finalize: 32 partials per batch -> (mu, rstd) -----------
__global__ void finalize_k(const float2* __restrict__ ps, float* __restrict__ stats) {
    int w = threadIdx.x >> 5, lane = threadIdx.x & 31;  // 2 warps, one per batch
    float2 p = ps[w * 32 + lane];
    float s = p.x, sq = p.y;
#pragma unroll
    for (int o = 16; o; o >>= 1) {
        s += __shfl_xor_sync(0xffffffffu, s, o);
        sq += __shfl_xor_sync(0xffffffffu, sq, o);
    }
    if (lane == 0) {
        float inv = 1.0f / (float)(TT_ * H_);
        float mu = s * inv;
        float var = sq * inv - mu * mu;
        stats[w * 2] = mu;
        stats[w * 2 + 1] = rsqrtf(var + EPS_);
    }
}

// ---------------- apply GN1 ----------------
__global__ void gnapply_k(const float* __restrict__ x, const float* __restrict__ g,
                          const float* __restrict__ bb, const float* __restrict__ stats,
                          float* __restrict__ y) {
    int i = blockIdx.x * 256 + threadIdx.x;
    int b = i >> 17;
    float mu = stats[b * 2], rs = stats[b * 2 + 1];
    int col = i & (H_ - 1);
    y[i] = (x[i] - mu) * rs * g[col] + bb[col];
}

// ============ fused logits, packed f32x2, h-split partials ================
// grid (TA/128=4, TT/32=4, B*HSPLIT=16). tile 32t x 128a, chunk of 128 h.
__global__ void logits_k(const float* __restrict__ tpart, const float* __restrict__ apart,
                         const float* __restrict__ w2, float* __restrict__ Lp) {
    __shared__ float Ts[32][33];     // [h][t]
    __shared__ float Am[32][130];    // [h][a]
    __shared__ float ws[32];
    int tid = threadIdx.x;           // 256
    int a0 = blockIdx.x * 128;
    int t0 = blockIdx.y * 32;
    int b  = blockIdx.z >> 3;
    int hc = blockIdx.z & 7;
    int h0 = hc * HCHUNK;
    int ty = tid >> 5;               // warp id 0..7 (t group)
    int tx = tid & 31;               // a lane

    const float* Tp = tpart + (b * TT_ + t0) * H_ + h0;
    const float* Ap = apart + (b * TA_ + a0) * H_ + h0;
    const float* Wp = w2 + h0;

    u64 acc[4][2] = {};
    int t_r = tid >> 3;              // 0..31 (t row)
    int t_c = (tid & 7) * 4;         // h cols 4
    int a_r = tid & 127;             // a row
    int a_g = tid >> 7;              // 0..1

    for (int hb = 0; hb < HCHUNK; hb += 32) {
        float4 tv = *reinterpret_cast<const float4*>(&Tp[t_r * H_ + hb + t_c]);
        Ts[t_c + 0][t_r] = tv.x; Ts[t_c + 1][t_r] = tv.y;
        Ts[t_c + 2][t_r] = tv.z; Ts[t_c + 3][t_r] = tv.w;
#pragma unroll
        for (int l = 0; l < 4; l++) {
            int c4 = (a_g * 4 + l) * 4;
            float4 av = *reinterpret_cast<const float4*>(&Ap[a_r * H_ + hb + c4]);
            Am[c4 + 0][a_r] = av.x; Am[c4 + 1][a_r] = av.y;
            Am[c4 + 2][a_r] = av.z; Am[c4 + 3][a_r] = av.w;
        }
        if (tid < 32) ws[tid] = Wp[hb + tid];
        __syncthreads();
#pragma unroll
        for (int hh = 0; hh < 32; hh++) {
            u64 wd = pack_dup(ws[hh]);
            u64 ap0 = *reinterpret_cast<const u64*>(&Am[hh][2 * tx]);
            u64 ap1 = *reinterpret_cast<const u64*>(&Am[hh][64 + 2 * tx]);
#pragma unroll
            for (int i = 0; i < 4; i++) {
                u64 td = pack_dup(Ts[hh][ty + i * 8]);
                u64 s0 = relu2(fadd2(td, ap0));
                u64 s1 = relu2(fadd2(td, ap1));
                ffma2(acc[i][0], s0, wd);
                ffma2(acc[i][1], s1, wd);
            }
        }
        __syncthreads();
    }
    float* Lrow = Lp + ((hc * B_ + b) * TT_ + t0) * TA_ + a0;
#pragma unroll
    for (int i = 0; i < 4; i++) {
        float2 p0 = unpack2(acc[i][0]);
        float2 p1 = unpack2(acc[i][1]);
        int t = ty + i * 8;
        *reinterpret_cast<float2*>(&Lrow[t * TA_ + 2 * tx]) = p0;
        *reinterpret_cast<float2*>(&Lrow[t * TA_ + 64 + 2 * tx]) = p1;
    }
}

// ---------------- softmax: sum partials + monotonic bias, over TA=512 -----
__global__ void softmax_k(const float* __restrict__ Lp, float* __restrict__ out) {
    __shared__ float wred[16];
    __shared__ float s_bcast;
    int row = blockIdx.x;            // b*TT + t
    int t = row & (TT_ - 1);
    int tid = threadIdx.x;           // a
    const float* p = Lp + row * TA_ + tid;
    float v = 0.f;
#pragma unroll
    for (int hc = 0; hc < HSPLIT; hc++)
        v += p[hc * (B_ * TT_ * TA_)];
    v += -0.1f * fabsf((float)tid - (float)t * 4.0f);

    float m = v;
#pragma unroll
    for (int o = 16; o; o >>= 1) m = fmaxf(m, __shfl_xor_sync(0xffffffffu, m, o));
    if ((tid & 31) == 0) wred[tid >> 5] = m;
    __syncthreads();
    if (tid == 0) {
        float mm = wred[0];
        for (int i = 1; i < 16; i++) mm = fmaxf(mm, wred[i]);
        s_bcast = mm;
    }
    __syncthreads();
    float mx = s_bcast;
    float e = expf(v - mx);
    float s = e;
#pragma unroll
    for (int o = 16; o; o >>= 1) s += __shfl_xor_sync(0xffffffffu, s, o);
    if ((tid & 31) == 0) wred[tid >> 5] = s;
    __syncthreads();
    if (tid == 0) {
        float ss = 0.f;
        for (int i = 0; i < 16; i++) ss += wred[i];
        s_bcast = ss;
    }
    __syncthreads();
    out[row * TA_ + tid] = e / s_bcast;
}

// ---------------- duration head: GN2 + 1x1 conv + softplus ----------------
__global__ void dur_k(const float* __restrict__ X2, const float* __restrict__ w3,
                      const float* __restrict__ b3,
                      const float* __restrict__ gng, const float* __restrict__ gnb,
                      const float* __restrict__ stats, float* __restrict__ out) {
    __shared__ float wred[8];
    int bt = blockIdx.x;
    int b = bt / TT_;
    float mu = stats[b * 2], rstd = stats[b * 2 + 1];
    const float* x = X2 + bt * H_;
    int tid = threadIdx.x;
    float s = 0.f;
    for (int i = tid; i < H_; i += 256) {
        float v = (x[i] - mu) * rstd * gng[i] + gnb[i];
        s += v * w3[i];
    }
#pragma unroll
    for (int o = 16; o; o >>= 1) s += __shfl_xor_sync(0xffffffffu, s, o);
    if ((tid & 31) == 0) wred[tid >> 5] = s;
    __syncthreads();
    if (tid == 0) {
        float ss = 0.f;
        for (int i = 0; i < 8; i++) ss += wred[i];
        float z = ss + b3[0];
        out[bt] = fmaxf(z, 0.f) + log1pf(expf(-fabsf(z)));
    }
}

// ---------------- launch ----------------
extern "C" void kernel_launch(void* const* d_in, const int* in_sizes, int n_in,
                              void* d_out, int out_size) {
    (void)in_sizes; (void)n_in; (void)out_size;
    const float* text  = (const float*)d_in[0];
    const float* audio = (const float*)d_in[1];
    const float* a_w1  = (const float*)d_in[2];
    const float* a_b1  = (const float*)d_in[3];
    const float* a_w2  = (const float*)d_in[4];
    const float* d_w1  = (const float*)d_in[6];
    const float* d_b1  = (const float*)d_in[7];
    const float* gn1g  = (const float*)d_in[8];
    const float* gn1b  = (const float*)d_in[9];
    const float* d_w2  = (const float*)d_in[10];
    const float* d_b2  = (const float*)d_in[11];
    const float* gn2g  = (const float*)d_in[12];
    const float* gn2b  = (const float*)d_in[13];
    const float* d_w3  = (const float*)d_in[14];
    const float* d_b3  = (const float*)d_in[15];
    float* out = (float*)d_out;

    float *tpart, *apart, *x1, *xn, *x2, *lp, *stats, *w1t, *w2t;
    float2* ps;
    cudaGetSymbolAddress((void**)&tpart,  g_tpart);
    cudaGetSymbolAddress((void**)&apart,  g_apart);
    cudaGetSymbolAddress((void**)&x1,     g_x1);
    cudaGetSymbolAddress((void**)&xn,     g_xn);
    cudaGetSymbolAddress((void**)&x2,     g_x2);
    cudaGetSymbolAddress((void**)&lp,     g_lp);
    cudaGetSymbolAddress((void**)&stats,  g_stats);
    cudaGetSymbolAddress((void**)&ps,     g_ps);
    cudaGetSymbolAddress((void**)&w1t,    g_w1t);
    cudaGetSymbolAddress((void**)&w2t,    g_w2t);

    cudaStream_t sDur;
    cudaStreamCreateWithFlags(&sDur, cudaStreamNonBlocking);
    cudaEvent_t evFork, evJoin;
    cudaEventCreateWithFlags(&evFork, cudaEventDisableTiming);
    cudaEventCreateWithFlags(&evJoin, cudaEventDisableTiming);
    cudaEventRecord(evFork, 0);
    cudaStreamWaitEvent(sDur, evFork, 0);

    // ---- duration path (side stream) ----
    dim3 tb(32, 8);
    dim3 tg(H_ / 32, H_ / 32);
    transpose_w_k<<<tg, tb, 0, sDur>>>(d_w1, w1t);
    transpose_w_k<<<tg, tb, 0, sDur>>>(d_w2, w2t);
    conv64_k<<<dim3(H_ / 64, (B_ * TT_) / 64), 256, 0, sDur>>>(text, w1t, d_b1, x1, ps);
    finalize_k<<<1, 64, 0, sDur>>>(ps, stats);
    gnapply_k<<<(B_ * TT_ * H_) / 256, 256, 0, sDur>>>(x1, gn1g, gn1b, stats, xn);
    conv64_k<<<dim3(H_ / 64, (B_ * TT_) / 64), 256, 0, sDur>>>(xn, w2t, d_b2, x2, ps + B_ * 32);
    finalize_k<<<1, 64, 0, sDur>>>(ps + B_ * 32, stats + 4);
    dur_k<<<B_ * TT_, 256, 0, sDur>>>(x2, d_w3, d_b3, gn2g, gn2b, stats + 4,
                                      out + B_ * TT_ * TA_);
    cudaEventRecord(evJoin, sDur);

    // ---- alignment path (main stream) ----
    gemm64_k<true><<<dim3(H_ / 64, (B_ * TT_) / 64), 256>>>(
        text, a_w1, a_b1, tpart, B_ * TT_, H_, H_);
    gemm64_k<false><<<dim3(H_ / 64, (B_ * TA_) / 64), 256>>>(
        audio, a_w1 + H_ * H_, nullptr, apart, B_ * TA_, H_, H_);
    logits_k<<<dim3(TA_ / 128, TT_ / 32, B_ * HSPLIT), 256>>>(tpart, apart, a_w2, lp);
    softmax_k<<<B_ * TT_, TA_>>>(lp, out);

    cudaStreamWaitEvent(0, evJoin, 0);
}

// round 7
// speedup vs baseline: 1.6591x; 1.0854x over previous
#include <cuda_runtime.h>
#include <math.h>

#define B_   2
#define TT_  128
#define TA_  512
#define H_   1024
#define EPS_ 1e-5f
#define HSPLIT 16
#define HCHUNK (H_ / HSPLIT)   // 64

typedef unsigned long long u64;

// ---------------- packed fp32x2 helpers (sm_103a) ----------------
__device__ __forceinline__ u64 pack_dup(float a) {
    u64 r; asm("mov.b64 %0, {%1,%1};" : "=l"(r) : "f"(a)); return r;
}
__device__ __forceinline__ float2 unpack2(u64 v) {
    float2 f; asm("mov.b64 {%0,%1}, %2;" : "=f"(f.x), "=f"(f.y) : "l"(v)); return f;
}
__device__ __forceinline__ void ffma2(u64& acc, u64 a, u64 b) {
    asm("fma.rn.f32x2 %0, %1, %2, %0;" : "+l"(acc) : "l"(a), "l"(b));
}
__device__ __forceinline__ u64 fadd2(u64 a, u64 b) {
    u64 r; asm("add.rn.f32x2 %0, %1, %2;" : "=l"(r) : "l"(a), "l"(b)); return r;
}
__device__ __forceinline__ u64 relu2(u64 v) {
    float2 f = unpack2(v);
    f.x = fmaxf(f.x, 0.f);
    f.y = fmaxf(f.y, 0.f);
    u64 r; asm("mov.b64 %0, {%1,%2};" : "=l"(r) : "f"(f.x), "f"(f.y));
    return r;
}

// ---------------- scratch ----------------
__device__ float g_tpart[B_ * TT_ * H_];
__device__ float g_apart[B_ * TA_ * H_];
__device__ float g_x1[B_ * TT_ * H_];
__device__ float g_x2[B_ * TT_ * H_];
__device__ float g_cp[2 * B_ * TT_ * H_];          // conv K-split partials
__device__ float g_lp[HSPLIT * B_ * TT_ * TA_];    // logits h-split partials
__device__ float g_stats[8];
__device__ float2 g_ps[2 * B_ * 128];              // stats partials [phase][b][slot]
__device__ float g_w1t[3 * H_ * H_];
__device__ float g_w2t[3 * H_ * H_];

// ---------------- weight transpose [O][I][3] -> [3][I][O] ----------------
__global__ void transpose_w_k(const float* __restrict__ W, float* __restrict__ Wt) {
    __shared__ float s[32][97];
    int o0 = blockIdx.x * 32;
    int i0 = blockIdx.y * 32;
    int tx = threadIdx.x, ty = threadIdx.y;
    for (int rr = ty; rr < 32; rr += 8)
        for (int cc = tx; cc < 96; cc += 32)
            s[rr][cc] = W[(o0 + rr) * 3 * H_ + i0 * 3 + cc];
    __syncthreads();
    for (int il = ty; il < 32; il += 8) {
#pragma unroll
        for (int k = 0; k < 3; k++)
            Wt[k * H_ * H_ + (i0 + il) * H_ + o0 + tx] = s[tx][il * 3 + k];
    }
}

// ============ 32x64 GEMM, TK=16, 256 thr, 2x4 micro, double-buffer =========
template <bool BIAS>
__global__ void gemm32_k(const float* __restrict__ A, const float* __restrict__ Bw,
                         const float* __restrict__ bias, float* __restrict__ C,
                         int M, int N, int K) {
    __shared__ __align__(16) float As[2][16][36];
    __shared__ __align__(16) float Bs[2][16][64];
    int tid = threadIdx.x;
    int m0 = blockIdx.y * 32;
    int n0 = blockIdx.x * 64;
    int tm = tid >> 4, tn = tid & 15;
    int ar = tid >> 3, ac = (tid & 7) * 2;
    int br = tid >> 4, bc = (tid & 15) * 4;

    const float* Aptr = A + (m0 + ar) * K + ac;
    const float* Bptr = Bw + br * N + n0 + bc;

    float2 a2 = *reinterpret_cast<const float2*>(Aptr);
    float4 b4 = *reinterpret_cast<const float4*>(Bptr);
    As[0][ac + 0][ar] = a2.x; As[0][ac + 1][ar] = a2.y;
    *reinterpret_cast<float4*>(&Bs[0][br][bc]) = b4;
    __syncthreads();

    u64 acc[2][2] = {};
    int buf = 0;
    for (int k0 = 0; k0 < K; k0 += 16) {
        bool more = (k0 + 16) < K;
        float2 a2n; float4 b4n;
        if (more) {
            a2n = *reinterpret_cast<const float2*>(Aptr + k0 + 16);
            b4n = *reinterpret_cast<const float4*>(Bptr + (k0 + 16) * N);
        }
#pragma unroll
        for (int kk = 0; kk < 16; kk++) {
            float a0 = As[buf][kk][tm * 2 + 0];
            float a1 = As[buf][kk][tm * 2 + 1];
            ulonglong2 bv = *reinterpret_cast<const ulonglong2*>(&Bs[buf][kk][tn * 4]);
            u64 A0 = pack_dup(a0), A1 = pack_dup(a1);
            ffma2(acc[0][0], A0, bv.x); ffma2(acc[0][1], A0, bv.y);
            ffma2(acc[1][0], A1, bv.x); ffma2(acc[1][1], A1, bv.y);
        }
        if (more) {
            int nb = buf ^ 1;
            As[nb][ac + 0][ar] = a2n.x; As[nb][ac + 1][ar] = a2n.y;
            *reinterpret_cast<float4*>(&Bs[nb][br][bc]) = b4n;
            __syncthreads();
            buf = nb;
        }
    }
    int n = n0 + tn * 4;
    float4 bv = BIAS ? *reinterpret_cast<const float4*>(&bias[n])
                     : make_float4(0.f, 0.f, 0.f, 0.f);
#pragma unroll
    for (int i = 0; i < 2; i++) {
        float2 p0 = unpack2(acc[i][0]);
        float2 p1 = unpack2(acc[i][1]);
        float4 v = make_float4(p0.x + bv.x, p0.y + bv.y, p1.x + bv.z, p1.y + bv.w);
        *reinterpret_cast<float4*>(&C[(m0 + tm * 2 + i) * N + n]) = v;
    }
}

// ============ conv1d(H,H,3) partial GEMM: K-split by grid.z, 32x64 tiles ===
template <bool GN>
__global__ void convp_k(const float* __restrict__ X, const float* __restrict__ Wt,
                        const float* __restrict__ gng, const float* __restrict__ gnb,
                        const float* __restrict__ stats, float* __restrict__ P) {
    __shared__ __align__(16) float As[2][16][36];
    __shared__ __align__(16) float Bs[2][16][64];
    int tid = threadIdx.x;
    int m0 = blockIdx.y * 32;
    int n0 = blockIdx.x * 64;
    int kz = blockIdx.z;
    int kbase = kz * 1536, kend = kbase + 1536;
    int tm = tid >> 4, tn = tid & 15;
    int ar = tid >> 3, ac = (tid & 7) * 2;
    int br = tid >> 4, bc = (tid & 15) * 4;

    int bt = m0 + ar;
    int b = bt >> 7;
    int tloc = bt & 127;
    const float* Xb = X + b * TT_ * H_;
    const float* Bptr = Wt + br * H_ + n0 + bc;
    float mu = 0.f, rs = 0.f;
    if (GN) { mu = stats[b * 2]; rs = stats[b * 2 + 1]; }

    float2 a2;
    {
        int kg = kbase;
        int ktap = kg >> 10;
        int koff = (kg & 1023) + ac;
        int tp = tloc + ktap - 1;
        a2 = make_float2(0.f, 0.f);
        if (tp >= 0 && tp < TT_) {
            a2 = *reinterpret_cast<const float2*>(&Xb[tp * H_ + koff]);
            if (GN) {
                a2.x = (a2.x - mu) * rs * gng[koff] + gnb[koff];
                a2.y = (a2.y - mu) * rs * gng[koff + 1] + gnb[koff + 1];
            }
        }
    }
    float4 b4 = *reinterpret_cast<const float4*>(Bptr + kbase * H_);
    As[0][ac + 0][ar] = a2.x; As[0][ac + 1][ar] = a2.y;
    *reinterpret_cast<float4*>(&Bs[0][br][bc]) = b4;
    __syncthreads();

    u64 acc[2][2] = {};
    int buf = 0;
    for (int k0 = kbase; k0 < kend; k0 += 16) {
        bool more = (k0 + 16) < kend;
        float2 a2n; float4 b4n;
        if (more) {
            int kg = k0 + 16;
            int ktap = kg >> 10;
            int koff = (kg & 1023) + ac;
            int tp = tloc + ktap - 1;
            a2n = make_float2(0.f, 0.f);
            if (tp >= 0 && tp < TT_) {
                a2n = *reinterpret_cast<const float2*>(&Xb[tp * H_ + koff]);
                if (GN) {
                    a2n.x = (a2n.x - mu) * rs * gng[koff] + gnb[koff];
                    a2n.y = (a2n.y - mu) * rs * gng[koff + 1] + gnb[koff + 1];
                }
            }
            b4n = *reinterpret_cast<const float4*>(Bptr + kg * H_);
        }
#pragma unroll
        for (int kk = 0; kk < 16; kk++) {
            float a0 = As[buf][kk][tm * 2 + 0];
            float a1 = As[buf][kk][tm * 2 + 1];
            ulonglong2 bv = *reinterpret_cast<const ulonglong2*>(&Bs[buf][kk][tn * 4]);
            u64 A0 = pack_dup(a0), A1 = pack_dup(a1);
            ffma2(acc[0][0], A0, bv.x); ffma2(acc[0][1], A0, bv.y);
            ffma2(acc[1][0], A1, bv.x); ffma2(acc[1][1], A1, bv.y);
        }
        if (more) {
            int nb = buf ^ 1;
            As[nb][ac + 0][ar] = a2n.x; As[nb][ac + 1][ar] = a2n.y;
            *reinterpret_cast<float4*>(&Bs[nb][br][bc]) = b4n;
            __syncthreads();
            buf = nb;
        }
    }
    float* Pz = P + kz * (B_ * TT_ * H_);
    int n = n0 + tn * 4;
#pragma unroll
    for (int i = 0; i < 2; i++) {
        float2 p0 = unpack2(acc[i][0]);
        float2 p1 = unpack2(acc[i][1]);
        float4 v = make_float4(p0.x, p0.y, p1.x, p1.y);
        *reinterpret_cast<float4*>(&Pz[(m0 + tm * 2 + i) * H_ + n]) = v;
    }
}

// ---------------- combine partials: relu(p0+p1+bias) + stats partials -----
__global__ void combine_k(const float* __restrict__ P, const float* __restrict__ bias,
                          float* __restrict__ Y, float2* __restrict__ ps) {
    __shared__ float2 red[8];
    int cta = blockIdx.x;
    int tid = threadIdx.x;
    int i4 = cta * 1024 + tid * 4;
    int col = i4 & (H_ - 1);
    float4 p0 = *reinterpret_cast<const float4*>(&P[i4]);
    float4 p1 = *reinterpret_cast<const float4*>(&P[B_ * TT_ * H_ + i4]);
    float4 bb = *reinterpret_cast<const float4*>(&bias[col]);
    float4 v = make_float4(fmaxf(p0.x + p1.x + bb.x, 0.f),
                           fmaxf(p0.y + p1.y + bb.y, 0.f),
                           fmaxf(p0.z + p1.z + bb.z, 0.f),
                           fmaxf(p0.w + p1.w + bb.w, 0.f));
    *reinterpret_cast<float4*>(&Y[i4]) = v;
    float s = v.x + v.y + v.z + v.w;
    float sq = v.x * v.x + v.y * v.y + v.z * v.z + v.w * v.w;
#pragma unroll
    for (int o = 16; o; o >>= 1) {
        s += __shfl_xor_sync(0xffffffffu, s, o);
        sq += __shfl_xor_sync(0xffffffffu, sq, o);
    }
    if ((tid & 31) == 0) red[tid >> 5] = make_float2(s, sq);
    __syncthreads();
    if (tid == 0) {
        float2 t = make_float2(0.f, 0.f);
        for (int i = 0; i < 8; i++) { t.x += red[i].x; t.y += red[i].y; }
        int b = cta >> 7;
        ps[b * 128 + (cta & 127)] = t;
    }
}

// ---------------- finalize: 128 partials per batch -> (mu, rstd) ----------
__global__ void finalize_k(const float2* __restrict__ ps, float* __restrict__ stats) {
    __shared__ float2 sh[8];
    int tid = threadIdx.x;
    int b = tid >> 7;
    float2 p = ps[b * 128 + (tid & 127)];
    float s = p.x, sq = p.y;
#pragma unroll
    for (int o = 16; o; o >>= 1) {
        s += __shfl_xor_sync(0xffffffffu, s, o);
        sq += __shfl_xor_sync(0xffffffffu, sq, o);
    }
    if ((tid & 31) == 0) sh[tid >> 5] = make_float2(s, sq);
    __syncthreads();
    if (tid < 2) {
        float ss = 0.f, ssq = 0.f;
        for (int i = 0; i < 4; i++) { ss += sh[tid * 4 + i].x; ssq += sh[tid * 4 + i].y; }
        float inv = 1.0f / (float)(TT_ * H_);
        float mu = ss * inv;
        float var = ssq * inv - mu * mu;
        stats[tid * 2] = mu;
        stats[tid * 2 + 1] = rsqrtf(var + EPS_);
    }
}

// ============ fused logits: 32t x 256a tile, h-chunk 64, dup'd smem =======
__global__ void logits_k(const float* __restrict__ tpart, const float* __restrict__ apart,
                         const float* __restrict__ w2, float* __restrict__ Lp) {
    __shared__ float Tsd[32][66];    // [h][2t] duplicated
    __shared__ float Am[32][258];    // [h][a]
    __shared__ float wsd[66];        // [2h] duplicated
    int tid = threadIdx.x;
    int a0 = blockIdx.x * 256;
    int t0 = blockIdx.y * 32;
    int b  = blockIdx.z >> 4;
    int hc = blockIdx.z & 15;
    int h0 = hc * HCHUNK;
    int ty = tid >> 5;
    int tx = tid & 31;

    const float* Tp = tpart + (b * TT_ + t0) * H_ + h0;
    const float* Ap = apart + (b * TA_ + a0) * H_ + h0;
    const float* Wp = w2 + h0;

    int t_r = tid >> 3;
    int t_c = (tid & 7) * 4;

    u64 acc[4][4] = {};
    for (int hb = 0; hb < HCHUNK; hb += 32) {
        float4 tv = *reinterpret_cast<const float4*>(&Tp[t_r * H_ + hb + t_c]);
        Tsd[t_c + 0][2 * t_r] = tv.x; Tsd[t_c + 0][2 * t_r + 1] = tv.x;
        Tsd[t_c + 1][2 * t_r] = tv.y; Tsd[t_c + 1][2 * t_r + 1] = tv.y;
        Tsd[t_c + 2][2 * t_r] = tv.z; Tsd[t_c + 2][2 * t_r + 1] = tv.z;
        Tsd[t_c + 3][2 * t_r] = tv.w; Tsd[t_c + 3][2 * t_r + 1] = tv.w;
#pragma unroll
        for (int l = 0; l < 8; l++) {
            float4 av = *reinterpret_cast<const float4*>(&Ap[tid * H_ + hb + l * 4]);
            Am[l * 4 + 0][tid] = av.x;
            Am[l * 4 + 1][tid] = av.y;
            Am[l * 4 + 2][tid] = av.z;
            Am[l * 4 + 3][tid] = av.w;
        }
        if (tid < 32) {
            float w = Wp[hb + tid];
            wsd[2 * tid] = w; wsd[2 * tid + 1] = w;
        }
        __syncthreads();
#pragma unroll
        for (int hh = 0; hh < 32; hh++) {
            u64 wd = *reinterpret_cast<const u64*>(&wsd[2 * hh]);
            u64 ap0 = *reinterpret_cast<const u64*>(&Am[hh][2 * tx]);
            u64 ap1 = *reinterpret_cast<const u64*>(&Am[hh][64 + 2 * tx]);
            u64 ap2 = *reinterpret_cast<const u64*>(&Am[hh][128 + 2 * tx]);
            u64 ap3 = *reinterpret_cast<const u64*>(&Am[hh][192 + 2 * tx]);
#pragma unroll
            for (int i = 0; i < 4; i++) {
                u64 td = *reinterpret_cast<const u64*>(&Tsd[hh][2 * (ty + 8 * i)]);
                ffma2(acc[i][0], relu2(fadd2(td, ap0)), wd);
                ffma2(acc[i][1], relu2(fadd2(td, ap1)), wd);
                ffma2(acc[i][2], relu2(fadd2(td, ap2)), wd);
                ffma2(acc[i][3], relu2(fadd2(td, ap3)), wd);
            }
        }
        __syncthreads();
    }
    float* L = Lp + hc * (B_ * TT_ * TA_) + (b * TT_ + t0) * TA_ + a0;
#pragma unroll
    for (int i = 0; i < 4; i++) {
        int r = ty + 8 * i;
#pragma unroll
        for (int j = 0; j < 4; j++) {
            float2 p = unpack2(acc[i][j]);
            *reinterpret_cast<float2*>(&L[r * TA_ + j * 64 + 2 * tx]) = p;
        }
    }
}

// ---------------- softmax: sum 16 partials + monotonic bias ----------------
__global__ void softmax_k(const float* __restrict__ Lp, float* __restrict__ out) {
    __shared__ float wred[16];
    __shared__ float s_bcast;
    int row = blockIdx.x;
    int t = row & (TT_ - 1);
    int tid = threadIdx.x;
    const float* p = Lp + row * TA_ + tid;
    float v = 0.f;
#pragma unroll
    for (int hcx = 0; hcx < HSPLIT; hcx++)
        v += p[hcx * (B_ * TT_ * TA_)];
    v += -0.1f * fabsf((float)tid - (float)t * 4.0f);

    float m = v;
#pragma unroll
    for (int o = 16; o; o >>= 1) m = fmaxf(m, __shfl_xor_sync(0xffffffffu, m, o));
    if ((tid & 31) == 0) wred[tid >> 5] = m;
    __syncthreads();
    if (tid == 0) {
        float mm = wred[0];
        for (int i = 1; i < 16; i++) mm = fmaxf(mm, wred[i]);
        s_bcast = mm;
    }
    __syncthreads();
    float mx = s_bcast;
    float e = expf(v - mx);
    float s = e;
#pragma unroll
    for (int o = 16; o; o >>= 1) s += __shfl_xor_sync(0xffffffffu, s, o);
    if ((tid & 31) == 0) wred[tid >> 5] = s;
    __syncthreads();
    if (tid == 0) {
        float ss = 0.f;
        for (int i = 0; i < 16; i++) ss += wred[i];
        s_bcast = ss;
    }
    __syncthreads();
    out[row * TA_ + tid] = e / s_bcast;
}

// ---------------- duration head: GN2 + 1x1 conv + softplus ----------------
__global__ void dur_k(const float* __restrict__ X2, const float* __restrict__ w3,
                      const float* __restrict__ b3,
                      const float* __restrict__ gng, const float* __restrict__ gnb,
                      const float* __restrict__ stats, float* __restrict__ out) {
    __shared__ float wred[8];
    int bt = blockIdx.x;
    int b = bt / TT_;
    float mu = stats[b * 2], rstd = stats[b * 2 + 1];
    const float* x = X2 + bt * H_;
    int tid = threadIdx.x;
    float s = 0.f;
    for (int i = tid; i < H_; i += 256) {
        float v = (x[i] - mu) * rstd * gng[i] + gnb[i];
        s += v * w3[i];
    }
#pragma unroll
    for (int o = 16; o; o >>= 1) s += __shfl_xor_sync(0xffffffffu, s, o);
    if ((tid & 31) == 0) wred[tid >> 5] = s;
    __syncthreads();
    if (tid == 0) {
        float ss = 0.f;
        for (int i = 0; i < 8; i++) ss += wred[i];
        float z = ss + b3[0];
        out[bt] = fmaxf(z, 0.f) + log1pf(expf(-fabsf(z)));
    }
}

// ---------------- launch (3-stream fork/join; destroy handles!) -----------
extern "C" void kernel_launch(void* const* d_in, const int* in_sizes, int n_in,
                              void* d_out, int out_size) {
    (void)in_sizes; (void)n_in; (void)out_size;
    const float* text  = (const float*)d_in[0];
    const float* audio = (const float*)d_in[1];
    const float* a_w1  = (const float*)d_in[2];
    const float* a_b1  = (const float*)d_in[3];
    const float* a_w2  = (const float*)d_in[4];
    const float* d_w1  = (const float*)d_in[6];
    const float* d_b1  = (const float*)d_in[7];
    const float* gn1g  = (const float*)d_in[8];
    const float* gn1b  = (const float*)d_in[9];
    const float* d_w2  = (const float*)d_in[10];
    const float* d_b2  = (const float*)d_in[11];
    const float* gn2g  = (const float*)d_in[12];
    const float* gn2b  = (const float*)d_in[13];
    const float* d_w3  = (const float*)d_in[14];
    const float* d_b3  = (const float*)d_in[15];
    float* out = (float*)d_out;

    float *tpart, *apart, *x1, *x2, *cp, *lp, *stats, *w1t, *w2t;
    float2* ps;
    cudaGetSymbolAddress((void**)&tpart,  g_tpart);
    cudaGetSymbolAddress((void**)&apart,  g_apart);
    cudaGetSymbolAddress((void**)&x1,     g_x1);
    cudaGetSymbolAddress((void**)&x2,     g_x2);
    cudaGetSymbolAddress((void**)&cp,     g_cp);
    cudaGetSymbolAddress((void**)&lp,     g_lp);
    cudaGetSymbolAddress((void**)&stats,  g_stats);
    cudaGetSymbolAddress((void**)&ps,     g_ps);
    cudaGetSymbolAddress((void**)&w1t,    g_w1t);
    cudaGetSymbolAddress((void**)&w2t,    g_w2t);

    cudaStream_t s1, s2;
    cudaStreamCreateWithFlags(&s1, cudaStreamNonBlocking);
    cudaStreamCreateWithFlags(&s2, cudaStreamNonBlocking);
    cudaEvent_t evFork, e1, e2;
    cudaEventCreateWithFlags(&evFork, cudaEventDisableTiming);
    cudaEventCreateWithFlags(&e1, cudaEventDisableTiming);
    cudaEventCreateWithFlags(&e2, cudaEventDisableTiming);
    cudaEventRecord(evFork, 0);
    cudaStreamWaitEvent(s1, evFork, 0);
    cudaStreamWaitEvent(s2, evFork, 0);

    // 1. tpart on s1
    gemm32_k<true><<<dim3(H_ / 64, (B_ * TT_) / 32), 256, 0, s1>>>(
        text, a_w1, a_b1, tpart, B_ * TT_, H_, H_);
    cudaEventRecord(e1, s1);
    // 2. apart on main
    gemm32_k<false><<<dim3(H_ / 64, (B_ * TA_) / 32), 256>>>(
        audio, a_w1 + H_ * H_, nullptr, apart, B_ * TA_, H_, H_);
    // 3,4. transposes on s2
    dim3 tb(32, 8);
    dim3 tg(H_ / 32, H_ / 32);
    transpose_w_k<<<tg, tb, 0, s2>>>(d_w1, w1t);
    transpose_w_k<<<tg, tb, 0, s2>>>(d_w2, w2t);
    // 5. conv1 partials on s2
    convp_k<false><<<dim3(H_ / 64, (B_ * TT_) / 32, 2), 256, 0, s2>>>(
        text, w1t, nullptr, nullptr, nullptr, cp);
    // 6. logits on main (after tpart + apart)
    cudaStreamWaitEvent(0, e1, 0);
    logits_k<<<dim3(TA_ / 256, TT_ / 32, B_ * HSPLIT), 256>>>(tpart, apart, a_w2, lp);
    // 7. softmax on main
    softmax_k<<<B_ * TT_, TA_>>>(lp, out);

    // rest of duration path on s2
    combine_k<<<256, 256, 0, s2>>>(cp, d_b1, x1, ps);
    finalize_k<<<1, 256, 0, s2>>>(ps, stats);
    convp_k<true><<<dim3(H_ / 64, (B_ * TT_) / 32, 2), 256, 0, s2>>>(
        x1, w2t, gn1g, gn1b, stats, cp);
    combine_k<<<256, 256, 0, s2>>>(cp, d_b2, x2, ps + B_ * 128);
    finalize_k<<<1, 256, 0, s2>>>(ps + B_ * 128, stats + 4);
    dur_k<<<B_ * TT_, 256, 0, s2>>>(x2, d_w3, d_b3, gn2g, gn2b, stats + 4,
                                    out + B_ * TT_ * TA_);
    cudaEventRecord(e2, s2);
    cudaStreamWaitEvent(0, e2, 0);

    // release handles — the captured graph keeps the dependency structure;
    // leaving these live trips the harness's memory-leak guard.
    cudaEventDestroy(evFork);
    cudaEventDestroy(e1);
    cudaEventDestroy(e2);
    cudaStreamDestroy(s1);
    cudaStreamDestroy(s2);
}

// round 8
// speedup vs baseline: 2.3008x; 1.3868x over previous
#include <cuda_runtime.h>
#include <math.h>

#define B_   2
#define TT_  128
#define TA_  512
#define H_   1024
#define EPS_ 1e-5f
#define HSPLIT 16
#define HCHUNK (H_ / HSPLIT)   // 64

typedef unsigned long long u64;

// ---------------- packed fp32x2 helpers (sm_103a) ----------------
__device__ __forceinline__ u64 pack_dup(float a) {
    u64 r; asm("mov.b64 %0, {%1,%1};" : "=l"(r) : "f"(a)); return r;
}
__device__ __forceinline__ float2 unpack2(u64 v) {
    float2 f; asm("mov.b64 {%0,%1}, %2;" : "=f"(f.x), "=f"(f.y) : "l"(v)); return f;
}
__device__ __forceinline__ void ffma2(u64& acc, u64 a, u64 b) {
    asm("fma.rn.f32x2 %0, %1, %2, %0;" : "+l"(acc) : "l"(a), "l"(b));
}
__device__ __forceinline__ u64 fadd2(u64 a, u64 b) {
    u64 r; asm("add.rn.f32x2 %0, %1, %2;" : "=l"(r) : "l"(a), "l"(b)); return r;
}
__device__ __forceinline__ u64 relu2(u64 v) {
    float2 f = unpack2(v);
    f.x = fmaxf(f.x, 0.f);
    f.y = fmaxf(f.y, 0.f);
    u64 r; asm("mov.b64 %0, {%1,%2};" : "=l"(r) : "f"(f.x), "f"(f.y));
    return r;
}

// ---------------- scratch ----------------
__device__ float g_tpart[B_ * TT_ * H_];
__device__ float g_apart[B_ * TA_ * H_];
__device__ float g_x1[B_ * TT_ * H_];
__device__ float g_x2[B_ * TT_ * H_];
__device__ float g_cp[3 * B_ * TT_ * H_];          // conv tap-split partials
__device__ float g_lp[HSPLIT * B_ * TT_ * TA_];    // logits h-split partials
__device__ float g_stats[8];
__device__ float2 g_ps[2 * B_ * 128];              // stats partials [phase][b][slot]
__device__ float g_w1t[3 * H_ * H_];
__device__ float g_w2t[3 * H_ * H_];

// ---------------- weight transpose [O][I][3] -> [3][I][O] ----------------
__global__ void transpose_w_k(const float* __restrict__ W, float* __restrict__ Wt) {
    __shared__ float s[32][97];
    int o0 = blockIdx.x * 32;
    int i0 = blockIdx.y * 32;
    int tx = threadIdx.x, ty = threadIdx.y;
    for (int rr = ty; rr < 32; rr += 8)
        for (int cc = tx; cc < 96; cc += 32)
            s[rr][cc] = W[(o0 + rr) * 3 * H_ + i0 * 3 + cc];
    __syncthreads();
    for (int il = ty; il < 32; il += 8) {
#pragma unroll
        for (int k = 0; k < 3; k++)
            Wt[k * H_ * H_ + (i0 + il) * H_ + o0 + tx] = s[tx][il * 3 + k];
    }
}

// ============ double-buffered 64x64 GEMM, TK=16, 256 thr, 4x4, FFMA2 =======
// 0.44 issue-slots per MAC: per kk = 2x LDS.128 + 4x MOV64 + 8x FFMA2 / 32 MACs
template <bool BIAS>
__global__ void gemm64_k(const float* __restrict__ A, const float* __restrict__ Bw,
                         const float* __restrict__ bias, float* __restrict__ C,
                         int M, int N, int K) {
    __shared__ __align__(16) float As[2][16][68];
    __shared__ __align__(16) float Bs[2][16][64];
    int tid = threadIdx.x;
    int m0 = blockIdx.y * 64;
    int n0 = blockIdx.x * 64;
    int tm = tid >> 4, tn = tid & 15;
    int ar = tid >> 2, ac = (tid & 3) * 4;
    int br = tid >> 4, bc = (tid & 15) * 4;

    const float* Aptr = A + (m0 + ar) * K + ac;
    const float* Bptr = Bw + br * N + n0 + bc;

    float4 a4 = *reinterpret_cast<const float4*>(Aptr);
    float4 b4 = *reinterpret_cast<const float4*>(Bptr);
    As[0][ac + 0][ar] = a4.x; As[0][ac + 1][ar] = a4.y;
    As[0][ac + 2][ar] = a4.z; As[0][ac + 3][ar] = a4.w;
    *reinterpret_cast<float4*>(&Bs[0][br][bc]) = b4;
    __syncthreads();

    u64 acc[4][2] = {};
    int buf = 0;
    for (int k0 = 0; k0 < K; k0 += 16) {
        bool more = (k0 + 16) < K;
        float4 a4n, b4n;
        if (more) {
            a4n = *reinterpret_cast<const float4*>(Aptr + k0 + 16);
            b4n = *reinterpret_cast<const float4*>(Bptr + (k0 + 16) * N);
        }
#pragma unroll
        for (int kk = 0; kk < 16; kk++) {
            float4 av = *reinterpret_cast<const float4*>(&As[buf][kk][tm * 4]);
            ulonglong2 bv = *reinterpret_cast<const ulonglong2*>(&Bs[buf][kk][tn * 4]);
            u64 a0 = pack_dup(av.x), a1 = pack_dup(av.y);
            u64 a2 = pack_dup(av.z), a3 = pack_dup(av.w);
            ffma2(acc[0][0], a0, bv.x); ffma2(acc[0][1], a0, bv.y);
            ffma2(acc[1][0], a1, bv.x); ffma2(acc[1][1], a1, bv.y);
            ffma2(acc[2][0], a2, bv.x); ffma2(acc[2][1], a2, bv.y);
            ffma2(acc[3][0], a3, bv.x); ffma2(acc[3][1], a3, bv.y);
        }
        if (more) {
            int nb = buf ^ 1;
            As[nb][ac + 0][ar] = a4n.x; As[nb][ac + 1][ar] = a4n.y;
            As[nb][ac + 2][ar] = a4n.z; As[nb][ac + 3][ar] = a4n.w;
            *reinterpret_cast<float4*>(&Bs[nb][br][bc]) = b4n;
            __syncthreads();
            buf = nb;
        }
    }
    int n = n0 + tn * 4;
    float4 bv = BIAS ? *reinterpret_cast<const float4*>(&bias[n])
                     : make_float4(0.f, 0.f, 0.f, 0.f);
#pragma unroll
    for (int i = 0; i < 4; i++) {
        float2 p0 = unpack2(acc[i][0]);
        float2 p1 = unpack2(acc[i][1]);
        float4 v = make_float4(p0.x + bv.x, p0.y + bv.y, p1.x + bv.z, p1.y + bv.w);
        *reinterpret_cast<float4*>(&C[(m0 + tm * 4 + i) * N + n]) = v;
    }
}

// ============ conv tap-split: P[kz] = shift(X, kz-1) @ Wt[kz], 64x64 tiles =
// grid (H/64=16, B*TT/64=4, 3 taps). Same inner loop as gemm64. Optional GN.
template <bool GN>
__global__ void convt_k(const float* __restrict__ X, const float* __restrict__ Wt,
                        const float* __restrict__ gng, const float* __restrict__ gnb,
                        const float* __restrict__ stats, float* __restrict__ P) {
    __shared__ __align__(16) float As[2][16][68];
    __shared__ __align__(16) float Bs[2][16][64];
    int tid = threadIdx.x;
    int m0 = blockIdx.y * 64;
    int n0 = blockIdx.x * 64;
    int kz = blockIdx.z;           // tap 0..2
    int tm = tid >> 4, tn = tid & 15;
    int ar = tid >> 2, ac = (tid & 3) * 4;
    int br = tid >> 4, bc = (tid & 15) * 4;

    int bt = m0 + ar;
    int b = bt >> 7;
    int tloc = bt & 127;
    int tp = tloc + kz - 1;
    bool inb = (tp >= 0) && (tp < TT_);
    const float* Arow = X + (b * TT_ + (inb ? tp : 0)) * H_ + ac;
    const float* Bptr = Wt + kz * H_ * H_ + br * H_ + n0 + bc;
    float mu = 0.f, rs = 0.f;
    if (GN) { mu = stats[b * 2]; rs = stats[b * 2 + 1]; }

    float4 a4 = make_float4(0.f, 0.f, 0.f, 0.f);
    if (inb) {
        a4 = *reinterpret_cast<const float4*>(Arow);
        if (GN) {
            float4 g4 = *reinterpret_cast<const float4*>(&gng[ac]);
            float4 bb4 = *reinterpret_cast<const float4*>(&gnb[ac]);
            a4.x = (a4.x - mu) * rs * g4.x + bb4.x;
            a4.y = (a4.y - mu) * rs * g4.y + bb4.y;
            a4.z = (a4.z - mu) * rs * g4.z + bb4.z;
            a4.w = (a4.w - mu) * rs * g4.w + bb4.w;
        }
    }
    float4 b4 = *reinterpret_cast<const float4*>(Bptr);
    As[0][ac + 0][ar] = a4.x; As[0][ac + 1][ar] = a4.y;
    As[0][ac + 2][ar] = a4.z; As[0][ac + 3][ar] = a4.w;
    *reinterpret_cast<float4*>(&Bs[0][br][bc]) = b4;
    __syncthreads();

    u64 acc[4][2] = {};
    int buf = 0;
    for (int k0 = 0; k0 < H_; k0 += 16) {
        bool more = (k0 + 16) < H_;
        float4 a4n = make_float4(0.f, 0.f, 0.f, 0.f);
        float4 b4n;
        if (more) {
            int kg = k0 + 16;
            if (inb) {
                a4n = *reinterpret_cast<const float4*>(Arow + kg);
                if (GN) {
                    int col = kg + ac;
                    float4 g4 = *reinterpret_cast<const float4*>(&gng[col]);
                    float4 bb4 = *reinterpret_cast<const float4*>(&gnb[col]);
                    a4n.x = (a4n.x - mu) * rs * g4.x + bb4.x;
                    a4n.y = (a4n.y - mu) * rs * g4.y + bb4.y;
                    a4n.z = (a4n.z - mu) * rs * g4.z + bb4.z;
                    a4n.w = (a4n.w - mu) * rs * g4.w + bb4.w;
                }
            }
            b4n = *reinterpret_cast<const float4*>(Bptr + kg * H_);
        }
#pragma unroll
        for (int kk = 0; kk < 16; kk++) {
            float4 av = *reinterpret_cast<const float4*>(&As[buf][kk][tm * 4]);
            ulonglong2 bv = *reinterpret_cast<const ulonglong2*>(&Bs[buf][kk][tn * 4]);
            u64 a0 = pack_dup(av.x), a1 = pack_dup(av.y);
            u64 a2 = pack_dup(av.z), a3 = pack_dup(av.w);
            ffma2(acc[0][0], a0, bv.x); ffma2(acc[0][1], a0, bv.y);
            ffma2(acc[1][0], a1, bv.x); ffma2(acc[1][1], a1, bv.y);
            ffma2(acc[2][0], a2, bv.x); ffma2(acc[2][1], a2, bv.y);
            ffma2(acc[3][0], a3, bv.x); ffma2(acc[3][1], a3, bv.y);
        }
        if (more) {
            int nb = buf ^ 1;
            As[nb][ac + 0][ar] = a4n.x; As[nb][ac + 1][ar] = a4n.y;
            As[nb][ac + 2][ar] = a4n.z; As[nb][ac + 3][ar] = a4n.w;
            *reinterpret_cast<float4*>(&Bs[nb][br][bc]) = b4n;
            __syncthreads();
            buf = nb;
        }
    }
    float* Pz = P + kz * (B_ * TT_ * H_);
    int n = n0 + tn * 4;
#pragma unroll
    for (int i = 0; i < 4; i++) {
        float2 p0 = unpack2(acc[i][0]);
        float2 p1 = unpack2(acc[i][1]);
        float4 v = make_float4(p0.x, p0.y, p1.x, p1.y);
        *reinterpret_cast<float4*>(&Pz[(m0 + tm * 4 + i) * H_ + n]) = v;
    }
}

// ---------------- combine 3 tap partials: relu(sum+bias) + stats ----------
__global__ void combine_k(const float* __restrict__ P, const float* __restrict__ bias,
                          float* __restrict__ Y, float2* __restrict__ ps) {
    __shared__ float2 red[8];
    int cta = blockIdx.x;
    int tid = threadIdx.x;
    int i4 = cta * 1024 + tid * 4;
    int col = i4 & (H_ - 1);
    const int SZ = B_ * TT_ * H_;
    float4 p0 = *reinterpret_cast<const float4*>(&P[i4]);
    float4 p1 = *reinterpret_cast<const float4*>(&P[SZ + i4]);
    float4 p2 = *reinterpret_cast<const float4*>(&P[2 * SZ + i4]);
    float4 bb = *reinterpret_cast<const float4*>(&bias[col]);
    float4 v = make_float4(fmaxf(p0.x + p1.x + p2.x + bb.x, 0.f),
                           fmaxf(p0.y + p1.y + p2.y + bb.y, 0.f),
                           fmaxf(p0.z + p1.z + p2.z + bb.z, 0.f),
                           fmaxf(p0.w + p1.w + p2.w + bb.w, 0.f));
    *reinterpret_cast<float4*>(&Y[i4]) = v;
    float s = v.x + v.y + v.z + v.w;
    float sq = v.x * v.x + v.y * v.y + v.z * v.z + v.w * v.w;
#pragma unroll
    for (int o = 16; o; o >>= 1) {
        s += __shfl_xor_sync(0xffffffffu, s, o);
        sq += __shfl_xor_sync(0xffffffffu, sq, o);
    }
    if ((tid & 31) == 0) red[tid >> 5] = make_float2(s, sq);
    __syncthreads();
    if (tid == 0) {
        float2 t = make_float2(0.f, 0.f);
        for (int i = 0; i < 8; i++) { t.x += red[i].x; t.y += red[i].y; }
        int b = cta >> 7;
        ps[b * 128 + (cta & 127)] = t;
    }
}

// ---------------- finalize: 128 partials per batch -> (mu, rstd) ----------
__global__ void finalize_k(const float2* __restrict__ ps, float* __restrict__ stats) {
    __shared__ float2 sh[8];
    int tid = threadIdx.x;
    int b = tid >> 7;
    float2 p = ps[b * 128 + (tid & 127)];
    float s = p.x, sq = p.y;
#pragma unroll
    for (int o = 16; o; o >>= 1) {
        s += __shfl_xor_sync(0xffffffffu, s, o);
        sq += __shfl_xor_sync(0xffffffffu, sq, o);
    }
    if ((tid & 31) == 0) sh[tid >> 5] = make_float2(s, sq);
    __syncthreads();
    if (tid < 2) {
        float ss = 0.f, ssq = 0.f;
        for (int i = 0; i < 4; i++) { ss += sh[tid * 4 + i].x; ssq += sh[tid * 4 + i].y; }
        float inv = 1.0f / (float)(TT_ * H_);
        float mu = ss * inv;
        float var = ssq * inv - mu * mu;
        stats[tid * 2] = mu;
        stats[tid * 2 + 1] = rsqrtf(var + EPS_);
    }
}

// ============ fused logits: 32t x 256a tile, h-chunk 64, dup'd smem =======
__global__ void logits_k(const float* __restrict__ tpart, const float* __restrict__ apart,
                         const float* __restrict__ w2, float* __restrict__ Lp) {
    __shared__ float Tsd[32][66];
    __shared__ float Am[32][258];
    __shared__ float wsd[66];
    int tid = threadIdx.x;
    int a0 = blockIdx.x * 256;
    int t0 = blockIdx.y * 32;
    int b  = blockIdx.z >> 4;
    int hc = blockIdx.z & 15;
    int h0 = hc * HCHUNK;
    int ty = tid >> 5;
    int tx = tid & 31;

    const float* Tp = tpart + (b * TT_ + t0) * H_ + h0;
    const float* Ap = apart + (b * TA_ + a0) * H_ + h0;
    const float* Wp = w2 + h0;

    int t_r = tid >> 3;
    int t_c = (tid & 7) * 4;

    u64 acc[4][4] = {};
    for (int hb = 0; hb < HCHUNK; hb += 32) {
        float4 tv = *reinterpret_cast<const float4*>(&Tp[t_r * H_ + hb + t_c]);
        Tsd[t_c + 0][2 * t_r] = tv.x; Tsd[t_c + 0][2 * t_r + 1] = tv.x;
        Tsd[t_c + 1][2 * t_r] = tv.y; Tsd[t_c + 1][2 * t_r + 1] = tv.y;
        Tsd[t_c + 2][2 * t_r] = tv.z; Tsd[t_c + 2][2 * t_r + 1] = tv.z;
        Tsd[t_c + 3][2 * t_r] = tv.w; Tsd[t_c + 3][2 * t_r + 1] = tv.w;
#pragma unroll
        for (int l = 0; l < 8; l++) {
            float4 av = *reinterpret_cast<const float4*>(&Ap[tid * H_ + hb + l * 4]);
            Am[l * 4 + 0][tid] = av.x;
            Am[l * 4 + 1][tid] = av.y;
            Am[l * 4 + 2][tid] = av.z;
            Am[l * 4 + 3][tid] = av.w;
        }
        if (tid < 32) {
            float w = Wp[hb + tid];
            wsd[2 * tid] = w; wsd[2 * tid + 1] = w;
        }
        __syncthreads();
#pragma unroll
        for (int hh = 0; hh < 32; hh++) {
            u64 wd = *reinterpret_cast<const u64*>(&wsd[2 * hh]);
            u64 ap0 = *reinterpret_cast<const u64*>(&Am[hh][2 * tx]);
            u64 ap1 = *reinterpret_cast<const u64*>(&Am[hh][64 + 2 * tx]);
            u64 ap2 = *reinterpret_cast<const u64*>(&Am[hh][128 + 2 * tx]);
            u64 ap3 = *reinterpret_cast<const u64*>(&Am[hh][192 + 2 * tx]);
#pragma unroll
            for (int i = 0; i < 4; i++) {
                u64 td = *reinterpret_cast<const u64*>(&Tsd[hh][2 * (ty + 8 * i)]);
                ffma2(acc[i][0], relu2(fadd2(td, ap0)), wd);
                ffma2(acc[i][1], relu2(fadd2(td, ap1)), wd);
                ffma2(acc[i][2], relu2(fadd2(td, ap2)), wd);
                ffma2(acc[i][3], relu2(fadd2(td, ap3)), wd);
            }
        }
        __syncthreads();
    }
    float* L = Lp + hc * (B_ * TT_ * TA_) + (b * TT_ + t0) * TA_ + a0;
#pragma unroll
    for (int i = 0; i < 4; i++) {
        int r = ty + 8 * i;
#pragma unroll
        for (int j = 0; j < 4; j++) {
            float2 p = unpack2(acc[i][j]);
            *reinterpret_cast<float2*>(&L[r * TA_ + j * 64 + 2 * tx]) = p;
        }
    }
}

// ---------------- softmax: sum 16 partials + monotonic bias ----------------
__global__ void softmax_k(const float* __restrict__ Lp, float* __restrict__ out) {
    __shared__ float wred[16];
    __shared__ float s_bcast;
    int row = blockIdx.x;
    int t = row & (TT_ - 1);
    int tid = threadIdx.x;
    const float* p = Lp + row * TA_ + tid;
    float v = 0.f;
#pragma unroll
    for (int hcx = 0; hcx < HSPLIT; hcx++)
        v += p[hcx * (B_ * TT_ * TA_)];
    v += -0.1f * fabsf((float)tid - (float)t * 4.0f);

    float m = v;
#pragma unroll
    for (int o = 16; o; o >>= 1) m = fmaxf(m, __shfl_xor_sync(0xffffffffu, m, o));
    if ((tid & 31) == 0) wred[tid >> 5] = m;
    __syncthreads();
    if (tid == 0) {
        float mm = wred[0];
        for (int i = 1; i < 16; i++) mm = fmaxf(mm, wred[i]);
        s_bcast = mm;
    }
    __syncthreads();
    float mx = s_bcast;
    float e = expf(v - mx);
    float s = e;
#pragma unroll
    for (int o = 16; o; o >>= 1) s += __shfl_xor_sync(0xffffffffu, s, o);
    if ((tid & 31) == 0) wred[tid >> 5] = s;
    __syncthreads();
    if (tid == 0) {
        float ss = 0.f;
        for (int i = 0; i < 16; i++) ss += wred[i];
        s_bcast = ss;
    }
    __syncthreads();
    out[row * TA_ + tid] = e / s_bcast;
}

// ---------------- duration head: GN2 + 1x1 conv + softplus ----------------
__global__ void dur_k(const float* __restrict__ X2, const float* __restrict__ w3,
                      const float* __restrict__ b3,
                      const float* __restrict__ gng, const float* __restrict__ gnb,
                      const float* __restrict__ stats, float* __restrict__ out) {
    __shared__ float wred[8];
    int bt = blockIdx.x;
    int b = bt / TT_;
    float mu = stats[b * 2], rstd = stats[b * 2 + 1];
    const float* x = X2 + bt * H_;
    int tid = threadIdx.x;
    float s = 0.f;
    for (int i = tid; i < H_; i += 256) {
        float v = (x[i] - mu) * rstd * gng[i] + gnb[i];
        s += v * w3[i];
    }
#pragma unroll
    for (int o = 16; o; o >>= 1) s += __shfl_xor_sync(0xffffffffu, s, o);
    if ((tid & 31) == 0) wred[tid >> 5] = s;
    __syncthreads();
    if (tid == 0) {
        float ss = 0.f;
        for (int i = 0; i < 8; i++) ss += wred[i];
        float z = ss + b3[0];
        out[bt] = fmaxf(z, 0.f) + log1pf(expf(-fabsf(z)));
    }
}

// ---------------- launch ----------------
extern "C" void kernel_launch(void* const* d_in, const int* in_sizes, int n_in,
                              void* d_out, int out_size) {
    (void)in_sizes; (void)n_in; (void)out_size;
    const float* text  = (const float*)d_in[0];
    const float* audio = (const float*)d_in[1];
    const float* a_w1  = (const float*)d_in[2];
    const float* a_b1  = (const float*)d_in[3];
    const float* a_w2  = (const float*)d_in[4];
    const float* d_w1  = (const float*)d_in[6];
    const float* d_b1  = (const float*)d_in[7];
    const float* gn1g  = (const float*)d_in[8];
    const float* gn1b  = (const float*)d_in[9];
    const float* d_w2  = (const float*)d_in[10];
    const float* d_b2  = (const float*)d_in[11];
    const float* gn2g  = (const float*)d_in[12];
    const float* gn2b  = (const float*)d_in[13];
    const float* d_w3  = (const float*)d_in[14];
    const float* d_b3  = (const float*)d_in[15];
    float* out = (float*)d_out;

    float *tpart, *apart, *x1, *x2, *cp, *lp, *stats, *w1t, *w2t;
    float2* ps;
    cudaGetSymbolAddress((void**)&tpart,  g_tpart);
    cudaGetSymbolAddress((void**)&apart,  g_apart);
    cudaGetSymbolAddress((void**)&x1,     g_x1);
    cudaGetSymbolAddress((void**)&x2,     g_x2);
    cudaGetSymbolAddress((void**)&cp,     g_cp);
    cudaGetSymbolAddress((void**)&lp,     g_lp);
    cudaGetSymbolAddress((void**)&stats,  g_stats);
    cudaGetSymbolAddress((void**)&ps,     g_ps);
    cudaGetSymbolAddress((void**)&w1t,    g_w1t);
    cudaGetSymbolAddress((void**)&w2t,    g_w2t);

    cudaStream_t s1, s2;
    cudaStreamCreateWithFlags(&s1, cudaStreamNonBlocking);
    cudaStreamCreateWithFlags(&s2, cudaStreamNonBlocking);
    cudaEvent_t evFork, e1, e2;
    cudaEventCreateWithFlags(&evFork, cudaEventDisableTiming);
    cudaEventCreateWithFlags(&e1, cudaEventDisableTiming);
    cudaEventCreateWithFlags(&e2, cudaEventDisableTiming);
    cudaEventRecord(evFork, 0);
    cudaStreamWaitEvent(s1, evFork, 0);
    cudaStreamWaitEvent(s2, evFork, 0);

    // s1: tpart (64 CTAs)
    gemm64_k<true><<<dim3(H_ / 64, (B_ * TT_) / 64), 256, 0, s1>>>(
        text, a_w1, a_b1, tpart, B_ * TT_, H_, H_);
    cudaEventRecord(e1, s1);
    // main: apart (256 CTAs)
    gemm64_k<false><<<dim3(H_ / 64, (B_ * TA_) / 64), 256>>>(
        audio, a_w1 + H_ * H_, nullptr, apart, B_ * TA_, H_, H_);
    // s2: duration path
    dim3 tb(32, 8);
    dim3 tg(H_ / 32, H_ / 32);
    transpose_w_k<<<tg, tb, 0, s2>>>(d_w1, w1t);
    transpose_w_k<<<tg, tb, 0, s2>>>(d_w2, w2t);
    convt_k<false><<<dim3(H_ / 64, (B_ * TT_) / 64, 3), 256, 0, s2>>>(
        text, w1t, nullptr, nullptr, nullptr, cp);
    combine_k<<<256, 256, 0, s2>>>(cp, d_b1, x1, ps);
    finalize_k<<<1, 256, 0, s2>>>(ps, stats);
    convt_k<true><<<dim3(H_ / 64, (B_ * TT_) / 64, 3), 256, 0, s2>>>(
        x1, w2t, gn1g, gn1b, stats, cp);
    combine_k<<<256, 256, 0, s2>>>(cp, d_b2, x2, ps + B_ * 128);
    finalize_k<<<1, 256, 0, s2>>>(ps + B_ * 128, stats + 4);
    dur_k<<<B_ * TT_, 256, 0, s2>>>(x2, d_w3, d_b3, gn2g, gn2b, stats + 4,
                                    out + B_ * TT_ * TA_);
    cudaEventRecord(e2, s2);

    // main: logits after tpart + apart
    cudaStreamWaitEvent(0, e1, 0);
    logits_k<<<dim3(TA_ / 256, TT_ / 32, B_ * HSPLIT), 256>>>(tpart, apart, a_w2, lp);
    softmax_k<<<B_ * TT_, TA_>>>(lp, out);

    cudaStreamWaitEvent(0, e2, 0);

    cudaEventDestroy(evFork);
    cudaEventDestroy(e1);
    cudaEventDestroy(e2);
    cudaStreamDestroy(s1);
    cudaStreamDestroy(s2);
}

// round 9
// speedup vs baseline: 2.5192x; 1.0949x over previous
#include <cuda_runtime.h>
#include <math.h>

#define B_   2
#define TT_  128
#define TA_  512
#define H_   1024
#define EPS_ 1e-5f
#define HSPLIT 16
#define HCHUNK (H_ / HSPLIT)   // 64

typedef unsigned long long u64;

// ---------------- packed fp32x2 helpers (sm_103a) ----------------
__device__ __forceinline__ u64 pack_dup(float a) {
    u64 r; asm("mov.b64 %0, {%1,%1};" : "=l"(r) : "f"(a)); return r;
}
__device__ __forceinline__ float2 unpack2(u64 v) {
    float2 f; asm("mov.b64 {%0,%1}, %2;" : "=f"(f.x), "=f"(f.y) : "l"(v)); return f;
}
__device__ __forceinline__ void ffma2(u64& acc, u64 a, u64 b) {
    asm("fma.rn.f32x2 %0, %1, %2, %0;" : "+l"(acc) : "l"(a), "l"(b));
}
__device__ __forceinline__ u64 fadd2(u64 a, u64 b) {
    u64 r; asm("add.rn.f32x2 %0, %1, %2;" : "=l"(r) : "l"(a), "l"(b)); return r;
}
__device__ __forceinline__ u64 relu2(u64 v) {
    float2 f = unpack2(v);
    f.x = fmaxf(f.x, 0.f);
    f.y = fmaxf(f.y, 0.f);
    u64 r; asm("mov.b64 %0, {%1,%2};" : "=l"(r) : "f"(f.x), "f"(f.y));
    return r;
}

// ---------------- scratch ----------------
__device__ float g_tpart[B_ * TT_ * H_];
__device__ float g_apart[B_ * TA_ * H_];
__device__ float g_cpA[2 * B_ * TA_ * H_];         // apart K-split partials
__device__ float g_x1[B_ * TT_ * H_];
__device__ float g_x2[B_ * TT_ * H_];
__device__ float g_cp[6 * B_ * TT_ * H_];          // conv tap+K split partials
__device__ float g_lp[HSPLIT * B_ * TT_ * TA_];    // logits h-split partials
__device__ float g_stats[8];
__device__ float2 g_ps[2 * B_ * 128];
__device__ float g_w1t[3 * H_ * H_];
__device__ float g_w2t[3 * H_ * H_];

// ---------------- weight transpose [O][I][3] -> [3][I][O] ----------------
__global__ void transpose_w_k(const float* __restrict__ W, float* __restrict__ Wt) {
    __shared__ float s[32][97];
    int o0 = blockIdx.x * 32;
    int i0 = blockIdx.y * 32;
    int tx = threadIdx.x, ty = threadIdx.y;
    for (int rr = ty; rr < 32; rr += 8)
        for (int cc = tx; cc < 96; cc += 32)
            s[rr][cc] = W[(o0 + rr) * 3 * H_ + i0 * 3 + cc];
    __syncthreads();
    for (int il = ty; il < 32; il += 8) {
#pragma unroll
        for (int k = 0; k < 3; k++)
            Wt[k * H_ * H_ + (i0 + il) * H_ + o0 + tx] = s[tx][il * 3 + k];
    }
}

// ============ double-buffered 64x64 GEMM body (shared by all variants) =====
// tiles: As [k][m] 16x68, Bs [k][n] 16x64. 256 thr, 4x4 micro via FFMA2.
template <bool BIAS>
__global__ void gemm64_k(const float* __restrict__ A, const float* __restrict__ Bw,
                         const float* __restrict__ bias, float* __restrict__ C,
                         int M, int N, int K) {
    __shared__ __align__(16) float As[2][16][68];
    __shared__ __align__(16) float Bs[2][16][64];
    int tid = threadIdx.x;
    int m0 = blockIdx.y * 64;
    int n0 = blockIdx.x * 64;
    int tm = tid >> 4, tn = tid & 15;
    int ar = tid >> 2, ac = (tid & 3) * 4;
    int br = tid >> 4, bc = (tid & 15) * 4;

    const float* Aptr = A + (m0 + ar) * K + ac;
    const float* Bptr = Bw + br * N + n0 + bc;

    float4 a4 = *reinterpret_cast<const float4*>(Aptr);
    float4 b4 = *reinterpret_cast<const float4*>(Bptr);
    As[0][ac + 0][ar] = a4.x; As[0][ac + 1][ar] = a4.y;
    As[0][ac + 2][ar] = a4.z; As[0][ac + 3][ar] = a4.w;
    *reinterpret_cast<float4*>(&Bs[0][br][bc]) = b4;
    __syncthreads();

    u64 acc[4][2] = {};
    int buf = 0;
    for (int k0 = 0; k0 < K; k0 += 16) {
        bool more = (k0 + 16) < K;
        float4 a4n, b4n;
        if (more) {
            a4n = *reinterpret_cast<const float4*>(Aptr + k0 + 16);
            b4n = *reinterpret_cast<const float4*>(Bptr + (k0 + 16) * N);
        }
#pragma unroll
        for (int kk = 0; kk < 16; kk++) {
            float4 av = *reinterpret_cast<const float4*>(&As[buf][kk][tm * 4]);
            ulonglong2 bv = *reinterpret_cast<const ulonglong2*>(&Bs[buf][kk][tn * 4]);
            u64 a0 = pack_dup(av.x), a1 = pack_dup(av.y);
            u64 a2 = pack_dup(av.z), a3 = pack_dup(av.w);
            ffma2(acc[0][0], a0, bv.x); ffma2(acc[0][1], a0, bv.y);
            ffma2(acc[1][0], a1, bv.x); ffma2(acc[1][1], a1, bv.y);
            ffma2(acc[2][0], a2, bv.x); ffma2(acc[2][1], a2, bv.y);
            ffma2(acc[3][0], a3, bv.x); ffma2(acc[3][1], a3, bv.y);
        }
        if (more) {
            int nb = buf ^ 1;
            As[nb][ac + 0][ar] = a4n.x; As[nb][ac + 1][ar] = a4n.y;
            As[nb][ac + 2][ar] = a4n.z; As[nb][ac + 3][ar] = a4n.w;
            *reinterpret_cast<float4*>(&Bs[nb][br][bc]) = b4n;
            __syncthreads();
            buf = nb;
        }
    }
    int n = n0 + tn * 4;
    float4 bv = BIAS ? *reinterpret_cast<const float4*>(&bias[n])
                     : make_float4(0.f, 0.f, 0.f, 0.f);
#pragma unroll
    for (int i = 0; i < 4; i++) {
        float2 p0 = unpack2(acc[i][0]);
        float2 p1 = unpack2(acc[i][1]);
        float4 v = make_float4(p0.x + bv.x, p0.y + bv.y, p1.x + bv.z, p1.y + bv.w);
        *reinterpret_cast<float4*>(&C[(m0 + tm * 4 + i) * N + n]) = v;
    }
}

// ============ K-split GEMM: z = K half, writes partial P[z] ================
__global__ void gemm64s_k(const float* __restrict__ A, const float* __restrict__ Bw,
                          float* __restrict__ P, int M, int N, int K) {
    __shared__ __align__(16) float As[2][16][68];
    __shared__ __align__(16) float Bs[2][16][64];
    int tid = threadIdx.x;
    int m0 = blockIdx.y * 64;
    int n0 = blockIdx.x * 64;
    int kz = blockIdx.z;
    int kh = K >> 1;
    int kbase = kz * kh;
    int tm = tid >> 4, tn = tid & 15;
    int ar = tid >> 2, ac = (tid & 3) * 4;
    int br = tid >> 4, bc = (tid & 15) * 4;

    const float* Aptr = A + (m0 + ar) * K + kbase + ac;
    const float* Bptr = Bw + (kbase + br) * N + n0 + bc;

    float4 a4 = *reinterpret_cast<const float4*>(Aptr);
    float4 b4 = *reinterpret_cast<const float4*>(Bptr);
    As[0][ac + 0][ar] = a4.x; As[0][ac + 1][ar] = a4.y;
    As[0][ac + 2][ar] = a4.z; As[0][ac + 3][ar] = a4.w;
    *reinterpret_cast<float4*>(&Bs[0][br][bc]) = b4;
    __syncthreads();

    u64 acc[4][2] = {};
    int buf = 0;
    for (int k0 = 0; k0 < kh; k0 += 16) {
        bool more = (k0 + 16) < kh;
        float4 a4n, b4n;
        if (more) {
            a4n = *reinterpret_cast<const float4*>(Aptr + k0 + 16);
            b4n = *reinterpret_cast<const float4*>(Bptr + (k0 + 16) * N);
        }
#pragma unroll
        for (int kk = 0; kk < 16; kk++) {
            float4 av = *reinterpret_cast<const float4*>(&As[buf][kk][tm * 4]);
            ulonglong2 bv = *reinterpret_cast<const ulonglong2*>(&Bs[buf][kk][tn * 4]);
            u64 a0 = pack_dup(av.x), a1 = pack_dup(av.y);
            u64 a2 = pack_dup(av.z), a3 = pack_dup(av.w);
            ffma2(acc[0][0], a0, bv.x); ffma2(acc[0][1], a0, bv.y);
            ffma2(acc[1][0], a1, bv.x); ffma2(acc[1][1], a1, bv.y);
            ffma2(acc[2][0], a2, bv.x); ffma2(acc[2][1], a2, bv.y);
            ffma2(acc[3][0], a3, bv.x); ffma2(acc[3][1], a3, bv.y);
        }
        if (more) {
            int nb = buf ^ 1;
            As[nb][ac + 0][ar] = a4n.x; As[nb][ac + 1][ar] = a4n.y;
            As[nb][ac + 2][ar] = a4n.z; As[nb][ac + 3][ar] = a4n.w;
            *reinterpret_cast<float4*>(&Bs[nb][br][bc]) = b4n;
            __syncthreads();
            buf = nb;
        }
    }
    float* Pz = P + kz * (M * N);
    int n = n0 + tn * 4;
#pragma unroll
    for (int i = 0; i < 4; i++) {
        float2 p0 = unpack2(acc[i][0]);
        float2 p1 = unpack2(acc[i][1]);
        float4 v = make_float4(p0.x, p0.y, p1.x, p1.y);
        *reinterpret_cast<float4*>(&Pz[(m0 + tm * 4 + i) * N + n]) = v;
    }
}

// ---------------- combine apart halves ----------------
__global__ void combineA_k(const float* __restrict__ P, float* __restrict__ Y, int SZ) {
    int i4 = (blockIdx.x * 256 + threadIdx.x) * 4;
    float4 p0 = *reinterpret_cast<const float4*>(&P[i4]);
    float4 p1 = *reinterpret_cast<const float4*>(&P[SZ + i4]);
    float4 v = make_float4(p0.x + p1.x, p0.y + p1.y, p0.z + p1.z, p0.w + p1.w);
    *reinterpret_cast<float4*>(&Y[i4]) = v;
}

// ============ conv tap+K split: z = tap*2 + khalf, 64x64 tiles =============
// grid (H/64=16, B*TT/64=4, 6). Optional GN on input load.
template <bool GN>
__global__ void convt_k(const float* __restrict__ X, const float* __restrict__ Wt,
                        const float* __restrict__ gng, const float* __restrict__ gnb,
                        const float* __restrict__ stats, float* __restrict__ P) {
    __shared__ __align__(16) float As[2][16][68];
    __shared__ __align__(16) float Bs[2][16][64];
    int tid = threadIdx.x;
    int m0 = blockIdx.y * 64;
    int n0 = blockIdx.x * 64;
    int z = blockIdx.z;
    int kz = z >> 1;               // tap 0..2
    int kbase = (z & 1) * 512;     // K half
    int tm = tid >> 4, tn = tid & 15;
    int ar = tid >> 2, ac = (tid & 3) * 4;
    int br = tid >> 4, bc = (tid & 15) * 4;

    int bt = m0 + ar;
    int b = bt >> 7;
    int tloc = bt & 127;
    int tp = tloc + kz - 1;
    bool inb = (tp >= 0) && (tp < TT_);
    const float* Arow = X + (b * TT_ + (inb ? tp : 0)) * H_ + kbase + ac;
    const float* Bptr = Wt + kz * H_ * H_ + (kbase + br) * H_ + n0 + bc;
    float mu = 0.f, rs = 0.f;
    if (GN) { mu = stats[b * 2]; rs = stats[b * 2 + 1]; }

    float4 a4 = make_float4(0.f, 0.f, 0.f, 0.f);
    if (inb) {
        a4 = *reinterpret_cast<const float4*>(Arow);
        if (GN) {
            int col = kbase + ac;
            float4 g4 = *reinterpret_cast<const float4*>(&gng[col]);
            float4 bb4 = *reinterpret_cast<const float4*>(&gnb[col]);
            a4.x = (a4.x - mu) * rs * g4.x + bb4.x;
            a4.y = (a4.y - mu) * rs * g4.y + bb4.y;
            a4.z = (a4.z - mu) * rs * g4.z + bb4.z;
            a4.w = (a4.w - mu) * rs * g4.w + bb4.w;
        }
    }
    float4 b4 = *reinterpret_cast<const float4*>(Bptr);
    As[0][ac + 0][ar] = a4.x; As[0][ac + 1][ar] = a4.y;
    As[0][ac + 2][ar] = a4.z; As[0][ac + 3][ar] = a4.w;
    *reinterpret_cast<float4*>(&Bs[0][br][bc]) = b4;
    __syncthreads();

    u64 acc[4][2] = {};
    int buf = 0;
    for (int k0 = 0; k0 < 512; k0 += 16) {
        bool more = (k0 + 16) < 512;
        float4 a4n = make_float4(0.f, 0.f, 0.f, 0.f);
        float4 b4n;
        if (more) {
            int kg = k0 + 16;
            if (inb) {
                a4n = *reinterpret_cast<const float4*>(Arow + kg);
                if (GN) {
                    int col = kbase + kg + ac;
                    float4 g4 = *reinterpret_cast<const float4*>(&gng[col]);
                    float4 bb4 = *reinterpret_cast<const float4*>(&gnb[col]);
                    a4n.x = (a4n.x - mu) * rs * g4.x + bb4.x;
                    a4n.y = (a4n.y - mu) * rs * g4.y + bb4.y;
                    a4n.z = (a4n.z - mu) * rs * g4.z + bb4.z;
                    a4n.w = (a4n.w - mu) * rs * g4.w + bb4.w;
                }
            }
            b4n = *reinterpret_cast<const float4*>(Bptr + kg * H_);
        }
#pragma unroll
        for (int kk = 0; kk < 16; kk++) {
            float4 av = *reinterpret_cast<const float4*>(&As[buf][kk][tm * 4]);
            ulonglong2 bv = *reinterpret_cast<const ulonglong2*>(&Bs[buf][kk][tn * 4]);
            u64 a0 = pack_dup(av.x), a1 = pack_dup(av.y);
            u64 a2 = pack_dup(av.z), a3 = pack_dup(av.w);
            ffma2(acc[0][0], a0, bv.x); ffma2(acc[0][1], a0, bv.y);
            ffma2(acc[1][0], a1, bv.x); ffma2(acc[1][1], a1, bv.y);
            ffma2(acc[2][0], a2, bv.x); ffma2(acc[2][1], a2, bv.y);
            ffma2(acc[3][0], a3, bv.x); ffma2(acc[3][1], a3, bv.y);
        }
        if (more) {
            int nb = buf ^ 1;
            As[nb][ac + 0][ar] = a4n.x; As[nb][ac + 1][ar] = a4n.y;
            As[nb][ac + 2][ar] = a4n.z; As[nb][ac + 3][ar] = a4n.w;
            *reinterpret_cast<float4*>(&Bs[nb][br][bc]) = b4n;
            __syncthreads();
            buf = nb;
        }
    }
    float* Pz = P + z * (B_ * TT_ * H_);
    int n = n0 + tn * 4;
#pragma unroll
    for (int i = 0; i < 4; i++) {
        float2 p0 = unpack2(acc[i][0]);
        float2 p1 = unpack2(acc[i][1]);
        float4 v = make_float4(p0.x, p0.y, p1.x, p1.y);
        *reinterpret_cast<float4*>(&Pz[(m0 + tm * 4 + i) * H_ + n]) = v;
    }
}

// ---------------- combine 6 partials: relu(sum+bias) + stats --------------
__global__ void combine6_k(const float* __restrict__ P, const float* __restrict__ bias,
                           float* __restrict__ Y, float2* __restrict__ ps) {
    __shared__ float2 red[8];
    int cta = blockIdx.x;
    int tid = threadIdx.x;
    int i4 = cta * 1024 + tid * 4;
    int col = i4 & (H_ - 1);
    const int SZ = B_ * TT_ * H_;
    float4 acc = *reinterpret_cast<const float4*>(&P[i4]);
#pragma unroll
    for (int z = 1; z < 6; z++) {
        float4 p = *reinterpret_cast<const float4*>(&P[z * SZ + i4]);
        acc.x += p.x; acc.y += p.y; acc.z += p.z; acc.w += p.w;
    }
    float4 bb = *reinterpret_cast<const float4*>(&bias[col]);
    float4 v = make_float4(fmaxf(acc.x + bb.x, 0.f), fmaxf(acc.y + bb.y, 0.f),
                           fmaxf(acc.z + bb.z, 0.f), fmaxf(acc.w + bb.w, 0.f));
    *reinterpret_cast<float4*>(&Y[i4]) = v;
    float s = v.x + v.y + v.z + v.w;
    float sq = v.x * v.x + v.y * v.y + v.z * v.z + v.w * v.w;
#pragma unroll
    for (int o = 16; o; o >>= 1) {
        s += __shfl_xor_sync(0xffffffffu, s, o);
        sq += __shfl_xor_sync(0xffffffffu, sq, o);
    }
    if ((tid & 31) == 0) red[tid >> 5] = make_float2(s, sq);
    __syncthreads();
    if (tid == 0) {
        float2 t = make_float2(0.f, 0.f);
        for (int i = 0; i < 8; i++) { t.x += red[i].x; t.y += red[i].y; }
        int b = cta >> 7;
        ps[b * 128 + (cta & 127)] = t;
    }
}

// ---------------- finalize: 128 partials per batch -> (mu, rstd) ----------
__global__ void finalize_k(const float2* __restrict__ ps, float* __restrict__ stats) {
    __shared__ float2 sh[8];
    int tid = threadIdx.x;
    int b = tid >> 7;
    float2 p = ps[b * 128 + (tid & 127)];
    float s = p.x, sq = p.y;
#pragma unroll
    for (int o = 16; o; o >>= 1) {
        s += __shfl_xor_sync(0xffffffffu, s, o);
        sq += __shfl_xor_sync(0xffffffffu, sq, o);
    }
    if ((tid & 31) == 0) sh[tid >> 5] = make_float2(s, sq);
    __syncthreads();
    if (tid < 2) {
        float ss = 0.f, ssq = 0.f;
        for (int i = 0; i < 4; i++) { ss += sh[tid * 4 + i].x; ssq += sh[tid * 4 + i].y; }
        float inv = 1.0f / (float)(TT_ * H_);
        float mu = ss * inv;
        float var = ssq * inv - mu * mu;
        stats[tid * 2] = mu;
        stats[tid * 2 + 1] = rsqrtf(var + EPS_);
    }
}

// ============ fused logits: 32t x 256a tile, h-chunk 64, dup'd smem =======
__global__ void logits_k(const float* __restrict__ tpart, const float* __restrict__ apart,
                         const float* __restrict__ w2, float* __restrict__ Lp) {
    __shared__ float Tsd[32][66];
    __shared__ float Am[32][258];
    __shared__ float wsd[66];
    int tid = threadIdx.x;
    int a0 = blockIdx.x * 256;
    int t0 = blockIdx.y * 32;
    int b  = blockIdx.z >> 4;
    int hc = blockIdx.z & 15;
    int h0 = hc * HCHUNK;
    int ty = tid >> 5;
    int tx = tid & 31;

    const float* Tp = tpart + (b * TT_ + t0) * H_ + h0;
    const float* Ap = apart + (b * TA_ + a0) * H_ + h0;
    const float* Wp = w2 + h0;

    int t_r = tid >> 3;
    int t_c = (tid & 7) * 4;

    u64 acc[4][4] = {};
    for (int hb = 0; hb < HCHUNK; hb += 32) {
        float4 tv = *reinterpret_cast<const float4*>(&Tp[t_r * H_ + hb + t_c]);
        Tsd[t_c + 0][2 * t_r] = tv.x; Tsd[t_c + 0][2 * t_r + 1] = tv.x;
        Tsd[t_c + 1][2 * t_r] = tv.y; Tsd[t_c + 1][2 * t_r + 1] = tv.y;
        Tsd[t_c + 2][2 * t_r] = tv.z; Tsd[t_c + 2][2 * t_r + 1] = tv.z;
        Tsd[t_c + 3][2 * t_r] = tv.w; Tsd[t_c + 3][2 * t_r + 1] = tv.w;
#pragma unroll
        for (int l = 0; l < 8; l++) {
            float4 av = *reinterpret_cast<const float4*>(&Ap[tid * H_ + hb + l * 4]);
            Am[l * 4 + 0][tid] = av.x;
            Am[l * 4 + 1][tid] = av.y;
            Am[l * 4 + 2][tid] = av.z;
            Am[l * 4 + 3][tid] = av.w;
        }
        if (tid < 32) {
            float w = Wp[hb + tid];
            wsd[2 * tid] = w; wsd[2 * tid + 1] = w;
        }
        __syncthreads();
#pragma unroll
        for (int hh = 0; hh < 32; hh++) {
            u64 wd = *reinterpret_cast<const u64*>(&wsd[2 * hh]);
            u64 ap0 = *reinterpret_cast<const u64*>(&Am[hh][2 * tx]);
            u64 ap1 = *reinterpret_cast<const u64*>(&Am[hh][64 + 2 * tx]);
            u64 ap2 = *reinterpret_cast<const u64*>(&Am[hh][128 + 2 * tx]);
            u64 ap3 = *reinterpret_cast<const u64*>(&Am[hh][192 + 2 * tx]);
#pragma unroll
            for (int i = 0; i < 4; i++) {
                u64 td = *reinterpret_cast<const u64*>(&Tsd[hh][2 * (ty + 8 * i)]);
                ffma2(acc[i][0], relu2(fadd2(td, ap0)), wd);
                ffma2(acc[i][1], relu2(fadd2(td, ap1)), wd);
                ffma2(acc[i][2], relu2(fadd2(td, ap2)), wd);
                ffma2(acc[i][3], relu2(fadd2(td, ap3)), wd);
            }
        }
        __syncthreads();
    }
    float* L = Lp + hc * (B_ * TT_ * TA_) + (b * TT_ + t0) * TA_ + a0;
#pragma unroll
    for (int i = 0; i < 4; i++) {
        int r = ty + 8 * i;
#pragma unroll
        for (int j = 0; j < 4; j++) {
            float2 p = unpack2(acc[i][j]);
            *reinterpret_cast<float2*>(&L[r * TA_ + j * 64 + 2 * tx]) = p;
        }
    }
}

// ---------------- softmax: sum 16 partials + monotonic bias ----------------
__global__ void softmax_k(const float* __restrict__ Lp, float* __restrict__ out) {
    __shared__ float wred[16];
    __shared__ float s_bcast;
    int row = blockIdx.x;
    int t = row & (TT_ - 1);
    int tid = threadIdx.x;
    const float* p = Lp + row * TA_ + tid;
    float v = 0.f;
#pragma unroll
    for (int hcx = 0; hcx < HSPLIT; hcx++)
        v += p[hcx * (B_ * TT_ * TA_)];
    v += -0.1f * fabsf((float)tid - (float)t * 4.0f);

    float m = v;
#pragma unroll
    for (int o = 16; o; o >>= 1) m = fmaxf(m, __shfl_xor_sync(0xffffffffu, m, o));
    if ((tid & 31) == 0) wred[tid >> 5] = m;
    __syncthreads();
    if (tid == 0) {
        float mm = wred[0];
        for (int i = 1; i < 16; i++) mm = fmaxf(mm, wred[i]);
        s_bcast = mm;
    }
    __syncthreads();
    float mx = s_bcast;
    float e = expf(v - mx);
    float s = e;
#pragma unroll
    for (int o = 16; o; o >>= 1) s += __shfl_xor_sync(0xffffffffu, s, o);
    if ((tid & 31) == 0) wred[tid >> 5] = s;
    __syncthreads();
    if (tid == 0) {
        float ss = 0.f;
        for (int i = 0; i < 16; i++) ss += wred[i];
        s_bcast = ss;
    }
    __syncthreads();
    out[row * TA_ + tid] = e / s_bcast;
}

// ---------------- duration head: GN2 + 1x1 conv + softplus ----------------
__global__ void dur_k(const float* __restrict__ X2, const float* __restrict__ w3,
                      const float* __restrict__ b3,
                      const float* __restrict__ gng, const float* __restrict__ gnb,
                      const float* __restrict__ stats, float* __restrict__ out) {
    __shared__ float wred[8];
    int bt = blockIdx.x;
    int b = bt / TT_;
    float mu = stats[b * 2], rstd = stats[b * 2 + 1];
    const float* x = X2 + bt * H_;
    int tid = threadIdx.x;
    float s = 0.f;
    for (int i = tid; i < H_; i += 256) {
        float v = (x[i] - mu) * rstd * gng[i] + gnb[i];
        s += v * w3[i];
    }
#pragma unroll
    for (int o = 16; o; o >>= 1) s += __shfl_xor_sync(0xffffffffu, s, o);
    if ((tid & 31) == 0) wred[tid >> 5] = s;
    __syncthreads();
    if (tid == 0) {
        float ss = 0.f;
        for (int i = 0; i < 8; i++) ss += wred[i];
        float z = ss + b3[0];
        out[bt] = fmaxf(z, 0.f) + log1pf(expf(-fabsf(z)));
    }
}

// ---------------- launch ----------------
extern "C" void kernel_launch(void* const* d_in, const int* in_sizes, int n_in,
                              void* d_out, int out_size) {
    (void)in_sizes; (void)n_in; (void)out_size;
    const float* text  = (const float*)d_in[0];
    const float* audio = (const float*)d_in[1];
    const float* a_w1  = (const float*)d_in[2];
    const float* a_b1  = (const float*)d_in[3];
    const float* a_w2  = (const float*)d_in[4];
    const float* d_w1  = (const float*)d_in[6];
    const float* d_b1  = (const float*)d_in[7];
    const float* gn1g  = (const float*)d_in[8];
    const float* gn1b  = (const float*)d_in[9];
    const float* d_w2  = (const float*)d_in[10];
    const float* d_b2  = (const float*)d_in[11];
    const float* gn2g  = (const float*)d_in[12];
    const float* gn2b  = (const float*)d_in[13];
    const float* d_w3  = (const float*)d_in[14];
    const float* d_b3  = (const float*)d_in[15];
    float* out = (float*)d_out;

    float *tpart, *apart, *cpA, *x1, *x2, *cp, *lp, *stats, *w1t, *w2t;
    float2* ps;
    cudaGetSymbolAddress((void**)&tpart,  g_tpart);
    cudaGetSymbolAddress((void**)&apart,  g_apart);
    cudaGetSymbolAddress((void**)&cpA,    g_cpA);
    cudaGetSymbolAddress((void**)&x1,     g_x1);
    cudaGetSymbolAddress((void**)&x2,     g_x2);
    cudaGetSymbolAddress((void**)&cp,     g_cp);
    cudaGetSymbolAddress((void**)&lp,     g_lp);
    cudaGetSymbolAddress((void**)&stats,  g_stats);
    cudaGetSymbolAddress((void**)&ps,     g_ps);
    cudaGetSymbolAddress((void**)&w1t,    g_w1t);
    cudaGetSymbolAddress((void**)&w2t,    g_w2t);

    cudaStream_t s1, s2;
    cudaStreamCreateWithFlags(&s1, cudaStreamNonBlocking);
    cudaStreamCreateWithFlags(&s2, cudaStreamNonBlocking);
    cudaEvent_t evFork, e1, e2, e3;
    cudaEventCreateWithFlags(&evFork, cudaEventDisableTiming);
    cudaEventCreateWithFlags(&e1, cudaEventDisableTiming);
    cudaEventCreateWithFlags(&e2, cudaEventDisableTiming);
    cudaEventCreateWithFlags(&e3, cudaEventDisableTiming);
    cudaEventRecord(evFork, 0);
    cudaStreamWaitEvent(s1, evFork, 0);
    cudaStreamWaitEvent(s2, evFork, 0);

    dim3 tb(32, 8);
    dim3 tg(H_ / 32, H_ / 32);

    // s1: transpose w2 (needed by conv2 on s2), then tpart
    transpose_w_k<<<tg, tb, 0, s1>>>(d_w2, w2t);
    cudaEventRecord(e3, s1);
    gemm64_k<true><<<dim3(H_ / 64, (B_ * TT_) / 64), 256, 0, s1>>>(
        text, a_w1, a_b1, tpart, B_ * TT_, H_, H_);
    cudaEventRecord(e1, s1);

    // main: apart K-split (512 CTAs) + combine
    gemm64s_k<<<dim3(H_ / 64, (B_ * TA_) / 64, 2), 256>>>(
        audio, a_w1 + H_ * H_, cpA, B_ * TA_, H_, H_);
    combineA_k<<<(B_ * TA_ * H_) / 1024, 256>>>(cpA, apart, B_ * TA_ * H_);

    // s2: duration path (conv K+tap split = 384 CTAs each)
    transpose_w_k<<<tg, tb, 0, s2>>>(d_w1, w1t);
    convt_k<false><<<dim3(H_ / 64, (B_ * TT_) / 64, 6), 256, 0, s2>>>(
        text, w1t, nullptr, nullptr, nullptr, cp);
    combine6_k<<<256, 256, 0, s2>>>(cp, d_b1, x1, ps);
    finalize_k<<<1, 256, 0, s2>>>(ps, stats);
    cudaStreamWaitEvent(s2, e3, 0);
    convt_k<true><<<dim3(H_ / 64, (B_ * TT_) / 64, 6), 256, 0, s2>>>(
        x1, w2t, gn1g, gn1b, stats, cp);
    combine6_k<<<256, 256, 0, s2>>>(cp, d_b2, x2, ps + B_ * 128);
    finalize_k<<<1, 256, 0, s2>>>(ps + B_ * 128, stats + 4);
    dur_k<<<B_ * TT_, 256, 0, s2>>>(x2, d_w3, d_b3, gn2g, gn2b, stats + 4,
                                    out + B_ * TT_ * TA_);
    cudaEventRecord(e2, s2);

    // main: logits after tpart (e1) + apart (in-stream)
    cudaStreamWaitEvent(0, e1, 0);
    logits_k<<<dim3(TA_ / 256, TT_ / 32, B_ * HSPLIT), 256>>>(tpart, apart, a_w2, lp);
    softmax_k<<<B_ * TT_, TA_>>>(lp, out);

    cudaStreamWaitEvent(0, e2, 0);

    cudaEventDestroy(evFork);
    cudaEventDestroy(e1);
    cudaEventDestroy(e2);
    cudaEventDestroy(e3);
    cudaStreamDestroy(s1);
    cudaStreamDestroy(s2);
}

// round 10
// speedup vs baseline: 2.5943x; 1.0298x over previous
#include <cuda_runtime.h>
#include <math.h>

#define B_   2
#define TT_  128
#define TA_  512
#define H_   1024
#define EPS_ 1e-5f
#define HSPLIT 16
#define HCHUNK (H_ / HSPLIT)   // 64

typedef unsigned long long u64;

// ---------------- packed fp32x2 helpers (sm_103a) ----------------
__device__ __forceinline__ u64 pack_dup(float a) {
    u64 r; asm("mov.b64 %0, {%1,%1};" : "=l"(r) : "f"(a)); return r;
}
__device__ __forceinline__ float2 unpack2(u64 v) {
    float2 f; asm("mov.b64 {%0,%1}, %2;" : "=f"(f.x), "=f"(f.y) : "l"(v)); return f;
}
__device__ __forceinline__ void ffma2(u64& acc, u64 a, u64 b) {
    asm("fma.rn.f32x2 %0, %1, %2, %0;" : "+l"(acc) : "l"(a), "l"(b));
}
__device__ __forceinline__ u64 fadd2(u64 a, u64 b) {
    u64 r; asm("add.rn.f32x2 %0, %1, %2;" : "=l"(r) : "l"(a), "l"(b)); return r;
}
__device__ __forceinline__ u64 relu2(u64 v) {
    float2 f = unpack2(v);
    f.x = fmaxf(f.x, 0.f);
    f.y = fmaxf(f.y, 0.f);
    u64 r; asm("mov.b64 %0, {%1,%2};" : "=l"(r) : "f"(f.x), "f"(f.y));
    return r;
}

// ---------------- scratch ----------------
__device__ float g_tpart[B_ * TT_ * H_];
__device__ float g_apart[B_ * TA_ * H_];
__device__ float g_cpA[4 * B_ * TA_ * H_];         // apart K-split partials
__device__ float g_cpT[4 * B_ * TT_ * H_];         // tpart K-split partials
__device__ float g_x1[B_ * TT_ * H_];
__device__ float g_x2[B_ * TT_ * H_];
__device__ float g_cp[12 * B_ * TT_ * H_];         // conv tap(3) x Ksplit(4) partials
__device__ float g_lp[HSPLIT * B_ * TT_ * TA_];    // logits h-split partials
__device__ float g_stats[8];
__device__ float2 g_ps[2 * B_ * 128];
__device__ float g_w1t[3 * H_ * H_];
__device__ float g_w2t[3 * H_ * H_];

// ---------------- weight transpose [O][I][3] -> [3][I][O] ----------------
__global__ void transpose_w_k(const float* __restrict__ W, float* __restrict__ Wt) {
    __shared__ float s[32][97];
    int o0 = blockIdx.x * 32;
    int i0 = blockIdx.y * 32;
    int tx = threadIdx.x, ty = threadIdx.y;
    for (int rr = ty; rr < 32; rr += 8)
        for (int cc = tx; cc < 96; cc += 32)
            s[rr][cc] = W[(o0 + rr) * 3 * H_ + i0 * 3 + cc];
    __syncthreads();
    for (int il = ty; il < 32; il += 8) {
#pragma unroll
        for (int k = 0; k < 3; k++)
            Wt[k * H_ * H_ + (i0 + il) * H_ + o0 + tx] = s[tx][il * 3 + k];
    }
}

// ============ 128x128 CTA tile, 8x8 micro, TK=16, 256 thr, K-split =========
// 1 B smem/MAC (vs 2 at 4x4). z selects K segment of kh=K/4; writes partial.
__global__ __launch_bounds__(256, 2)
void gemm128s_k(const float* __restrict__ A, const float* __restrict__ Bw,
                float* __restrict__ P, int M, int N, int K) {
    __shared__ __align__(16) float As[2][16][132];
    __shared__ __align__(16) float Bs[2][16][128];
    int tid = threadIdx.x;
    int m0 = blockIdx.y * 128;
    int n0 = blockIdx.x * 128;
    int kz = blockIdx.z;
    int kh = K >> 2;
    int kbase = kz * kh;
    int tm = tid >> 4, tn = tid & 15;           // 16x16 thread grid, 8x8 each
    int ar = tid >> 1, ac = (tid & 1) * 8;      // A loader: row, 8 k
    int br = tid >> 4, bc = (tid & 15) * 8;     // B loader: k row, 8 n

    const float* Aptr = A + (m0 + ar) * K + kbase + ac;
    const float* Bptr = Bw + (kbase + br) * N + n0 + bc;

    // prologue
    {
        float4 a0 = *reinterpret_cast<const float4*>(Aptr);
        float4 a1 = *reinterpret_cast<const float4*>(Aptr + 4);
        As[0][ac + 0][ar] = a0.x; As[0][ac + 1][ar] = a0.y;
        As[0][ac + 2][ar] = a0.z; As[0][ac + 3][ar] = a0.w;
        As[0][ac + 4][ar] = a1.x; As[0][ac + 5][ar] = a1.y;
        As[0][ac + 6][ar] = a1.z; As[0][ac + 7][ar] = a1.w;
        float4 b0 = *reinterpret_cast<const float4*>(Bptr);
        float4 b1 = *reinterpret_cast<const float4*>(Bptr + 4);
        *reinterpret_cast<float4*>(&Bs[0][br][bc]) = b0;
        *reinterpret_cast<float4*>(&Bs[0][br][bc + 4]) = b1;
    }
    __syncthreads();

    u64 acc[8][4] = {};
    int buf = 0;
    for (int k0 = 0; k0 < kh; k0 += 16) {
        bool more = (k0 + 16) < kh;
        float4 a0n, a1n, b0n, b1n;
        if (more) {
            a0n = *reinterpret_cast<const float4*>(Aptr + k0 + 16);
            a1n = *reinterpret_cast<const float4*>(Aptr + k0 + 20);
            b0n = *reinterpret_cast<const float4*>(Bptr + (k0 + 16) * N);
            b1n = *reinterpret_cast<const float4*>(Bptr + (k0 + 16) * N + 4);
        }
#pragma unroll
        for (int kk = 0; kk < 16; kk++) {
            float4 av0 = *reinterpret_cast<const float4*>(&As[buf][kk][tm * 8]);
            float4 av1 = *reinterpret_cast<const float4*>(&As[buf][kk][tm * 8 + 4]);
            ulonglong2 bv0 = *reinterpret_cast<const ulonglong2*>(&Bs[buf][kk][tn * 8]);
            ulonglong2 bv1 = *reinterpret_cast<const ulonglong2*>(&Bs[buf][kk][tn * 8 + 4]);
            u64 ad[8];
            ad[0] = pack_dup(av0.x); ad[1] = pack_dup(av0.y);
            ad[2] = pack_dup(av0.z); ad[3] = pack_dup(av0.w);
            ad[4] = pack_dup(av1.x); ad[5] = pack_dup(av1.y);
            ad[6] = pack_dup(av1.z); ad[7] = pack_dup(av1.w);
#pragma unroll
            for (int i = 0; i < 8; i++) {
                ffma2(acc[i][0], ad[i], bv0.x);
                ffma2(acc[i][1], ad[i], bv0.y);
                ffma2(acc[i][2], ad[i], bv1.x);
                ffma2(acc[i][3], ad[i], bv1.y);
            }
        }
        if (more) {
            int nb = buf ^ 1;
            As[nb][ac + 0][ar] = a0n.x; As[nb][ac + 1][ar] = a0n.y;
            As[nb][ac + 2][ar] = a0n.z; As[nb][ac + 3][ar] = a0n.w;
            As[nb][ac + 4][ar] = a1n.x; As[nb][ac + 5][ar] = a1n.y;
            As[nb][ac + 6][ar] = a1n.z; As[nb][ac + 7][ar] = a1n.w;
            *reinterpret_cast<float4*>(&Bs[nb][br][bc]) = b0n;
            *reinterpret_cast<float4*>(&Bs[nb][br][bc + 4]) = b1n;
            __syncthreads();
            buf = nb;
        }
    }
    float* Pz = P + kz * (M * N);
    int n = n0 + tn * 8;
#pragma unroll
    for (int i = 0; i < 8; i++) {
        int m = m0 + tm * 8 + i;
        float2 p0 = unpack2(acc[i][0]);
        float2 p1 = unpack2(acc[i][1]);
        float2 p2 = unpack2(acc[i][2]);
        float2 p3 = unpack2(acc[i][3]);
        *reinterpret_cast<float4*>(&Pz[m * N + n]) =
            make_float4(p0.x, p0.y, p1.x, p1.y);
        *reinterpret_cast<float4*>(&Pz[m * N + n + 4]) =
            make_float4(p2.x, p2.y, p3.x, p3.y);
    }
}

// ---------------- combine 4 K-split partials (+optional bias) -------------
template <bool BIAS>
__global__ void combine4_k(const float* __restrict__ P, const float* __restrict__ bias,
                           float* __restrict__ Y, int SZ) {
    int i4 = (blockIdx.x * 256 + threadIdx.x) * 4;
    float4 acc = *reinterpret_cast<const float4*>(&P[i4]);
#pragma unroll
    for (int z = 1; z < 4; z++) {
        float4 p = *reinterpret_cast<const float4*>(&P[z * SZ + i4]);
        acc.x += p.x; acc.y += p.y; acc.z += p.z; acc.w += p.w;
    }
    if (BIAS) {
        int col = i4 & (H_ - 1);
        float4 bb = *reinterpret_cast<const float4*>(&bias[col]);
        acc.x += bb.x; acc.y += bb.y; acc.z += bb.z; acc.w += bb.w;
    }
    *reinterpret_cast<float4*>(&Y[i4]) = acc;
}

// ============ conv: 128x128 tile, 8x8 micro, z = tap*4 + kq ================
// grid (8, 2, 12). kh=256 per segment. Optional GN on input load.
template <bool GN>
__global__ __launch_bounds__(256, 2)
void convt128_k(const float* __restrict__ X, const float* __restrict__ Wt,
                const float* __restrict__ gng, const float* __restrict__ gnb,
                const float* __restrict__ stats, float* __restrict__ P) {
    __shared__ __align__(16) float As[2][16][132];
    __shared__ __align__(16) float Bs[2][16][128];
    int tid = threadIdx.x;
    int m0 = blockIdx.y * 128;
    int n0 = blockIdx.x * 128;
    int z = blockIdx.z;
    int tap = z >> 2;
    int kbase = (z & 3) * 256;
    int tm = tid >> 4, tn = tid & 15;
    int ar = tid >> 1, ac = (tid & 1) * 8;
    int br = tid >> 4, bc = (tid & 15) * 8;

    int bt = m0 + ar;
    int b = bt >> 7;
    int tloc = bt & 127;
    int tp = tloc + tap - 1;
    bool inb = (tp >= 0) && (tp < TT_);
    const float* Arow = X + (b * TT_ + (inb ? tp : 0)) * H_ + kbase + ac;
    const float* Bptr = Wt + tap * H_ * H_ + (kbase + br) * H_ + n0 + bc;
    float mu = 0.f, rs = 0.f;
    if (GN) { mu = stats[b * 2]; rs = stats[b * 2 + 1]; }

    // prologue
    {
        float4 a0 = make_float4(0.f, 0.f, 0.f, 0.f), a1 = a0;
        if (inb) {
            a0 = *reinterpret_cast<const float4*>(Arow);
            a1 = *reinterpret_cast<const float4*>(Arow + 4);
            if (GN) {
                int col = kbase + ac;
                float4 g0 = *reinterpret_cast<const float4*>(&gng[col]);
                float4 g1 = *reinterpret_cast<const float4*>(&gng[col + 4]);
                float4 c0 = *reinterpret_cast<const float4*>(&gnb[col]);
                float4 c1 = *reinterpret_cast<const float4*>(&gnb[col + 4]);
                a0.x = (a0.x - mu) * rs * g0.x + c0.x;
                a0.y = (a0.y - mu) * rs * g0.y + c0.y;
                a0.z = (a0.z - mu) * rs * g0.z + c0.z;
                a0.w = (a0.w - mu) * rs * g0.w + c0.w;
                a1.x = (a1.x - mu) * rs * g1.x + c1.x;
                a1.y = (a1.y - mu) * rs * g1.y + c1.y;
                a1.z = (a1.z - mu) * rs * g1.z + c1.z;
                a1.w = (a1.w - mu) * rs * g1.w + c1.w;
            }
        }
        As[0][ac + 0][ar] = a0.x; As[0][ac + 1][ar] = a0.y;
        As[0][ac + 2][ar] = a0.z; As[0][ac + 3][ar] = a0.w;
        As[0][ac + 4][ar] = a1.x; As[0][ac + 5][ar] = a1.y;
        As[0][ac + 6][ar] = a1.z; As[0][ac + 7][ar] = a1.w;
        float4 b0 = *reinterpret_cast<const float4*>(Bptr);
        float4 b1 = *reinterpret_cast<const float4*>(Bptr + 4);
        *reinterpret_cast<float4*>(&Bs[0][br][bc]) = b0;
        *reinterpret_cast<float4*>(&Bs[0][br][bc + 4]) = b1;
    }
    __syncthreads();

    u64 acc[8][4] = {};
    int buf = 0;
    for (int k0 = 0; k0 < 256; k0 += 16) {
        bool more = (k0 + 16) < 256;
        float4 a0n = make_float4(0.f, 0.f, 0.f, 0.f), a1n = a0n;
        float4 b0n, b1n;
        if (more) {
            int kg = k0 + 16;
            if (inb) {
                a0n = *reinterpret_cast<const float4*>(Arow + kg);
                a1n = *reinterpret_cast<const float4*>(Arow + kg + 4);
                if (GN) {
                    int col = kbase + kg + ac;
                    float4 g0 = *reinterpret_cast<const float4*>(&gng[col]);
                    float4 g1 = *reinterpret_cast<const float4*>(&gng[col + 4]);
                    float4 c0 = *reinterpret_cast<const float4*>(&gnb[col]);
                    float4 c1 = *reinterpret_cast<const float4*>(&gnb[col + 4]);
                    a0n.x = (a0n.x - mu) * rs * g0.x + c0.x;
                    a0n.y = (a0n.y - mu) * rs * g0.y + c0.y;
                    a0n.z = (a0n.z - mu) * rs * g0.z + c0.z;
                    a0n.w = (a0n.w - mu) * rs * g0.w + c0.w;
                    a1n.x = (a1n.x - mu) * rs * g1.x + c1.x;
                    a1n.y = (a1n.y - mu) * rs * g1.y + c1.y;
                    a1n.z = (a1n.z - mu) * rs * g1.z + c1.z;
                    a1n.w = (a1n.w - mu) * rs * g1.w + c1.w;
                }
            }
            b0n = *reinterpret_cast<const float4*>(Bptr + kg * H_);
            b1n = *reinterpret_cast<const float4*>(Bptr + kg * H_ + 4);
        }
#pragma unroll
        for (int kk = 0; kk < 16; kk++) {
            float4 av0 = *reinterpret_cast<const float4*>(&As[buf][kk][tm * 8]);
            float4 av1 = *reinterpret_cast<const float4*>(&As[buf][kk][tm * 8 + 4]);
            ulonglong2 bv0 = *reinterpret_cast<const ulonglong2*>(&Bs[buf][kk][tn * 8]);
            ulonglong2 bv1 = *reinterpret_cast<const ulonglong2*>(&Bs[buf][kk][tn * 8 + 4]);
            u64 ad[8];
            ad[0] = pack_dup(av0.x); ad[1] = pack_dup(av0.y);
            ad[2] = pack_dup(av0.z); ad[3] = pack_dup(av0.w);
            ad[4] = pack_dup(av1.x); ad[5] = pack_dup(av1.y);
            ad[6] = pack_dup(av1.z); ad[7] = pack_dup(av1.w);
#pragma unroll
            for (int i = 0; i < 8; i++) {
                ffma2(acc[i][0], ad[i], bv0.x);
                ffma2(acc[i][1], ad[i], bv0.y);
                ffma2(acc[i][2], ad[i], bv1.x);
                ffma2(acc[i][3], ad[i], bv1.y);
            }
        }
        if (more) {
            int nb = buf ^ 1;
            As[nb][ac + 0][ar] = a0n.x; As[nb][ac + 1][ar] = a0n.y;
            As[nb][ac + 2][ar] = a0n.z; As[nb][ac + 3][ar] = a0n.w;
            As[nb][ac + 4][ar] = a1n.x; As[nb][ac + 5][ar] = a1n.y;
            As[nb][ac + 6][ar] = a1n.z; As[nb][ac + 7][ar] = a1n.w;
            *reinterpret_cast<float4*>(&Bs[nb][br][bc]) = b0n;
            *reinterpret_cast<float4*>(&Bs[nb][br][bc + 4]) = b1n;
            __syncthreads();
            buf = nb;
        }
    }
    float* Pz = P + z * (B_ * TT_ * H_);
    int n = n0 + tn * 8;
#pragma unroll
    for (int i = 0; i < 8; i++) {
        int m = m0 + tm * 8 + i;
        float2 p0 = unpack2(acc[i][0]);
        float2 p1 = unpack2(acc[i][1]);
        float2 p2 = unpack2(acc[i][2]);
        float2 p3 = unpack2(acc[i][3]);
        *reinterpret_cast<float4*>(&Pz[m * H_ + n]) =
            make_float4(p0.x, p0.y, p1.x, p1.y);
        *reinterpret_cast<float4*>(&Pz[m * H_ + n + 4]) =
            make_float4(p2.x, p2.y, p3.x, p3.y);
    }
}

// ---------------- combine 12 partials: relu(sum+bias) + stats -------------
__global__ void combine12_k(const float* __restrict__ P, const float* __restrict__ bias,
                            float* __restrict__ Y, float2* __restrict__ ps) {
    __shared__ float2 red[8];
    int cta = blockIdx.x;
    int tid = threadIdx.x;
    int i4 = cta * 1024 + tid * 4;
    int col = i4 & (H_ - 1);
    const int SZ = B_ * TT_ * H_;
    float4 acc = *reinterpret_cast<const float4*>(&P[i4]);
#pragma unroll
    for (int z = 1; z < 12; z++) {
        float4 p = *reinterpret_cast<const float4*>(&P[z * SZ + i4]);
        acc.x += p.x; acc.y += p.y; acc.z += p.z; acc.w += p.w;
    }
    float4 bb = *reinterpret_cast<const float4*>(&bias[col]);
    float4 v = make_float4(fmaxf(acc.x + bb.x, 0.f), fmaxf(acc.y + bb.y, 0.f),
                           fmaxf(acc.z + bb.z, 0.f), fmaxf(acc.w + bb.w, 0.f));
    *reinterpret_cast<float4*>(&Y[i4]) = v;
    float s = v.x + v.y + v.z + v.w;
    float sq = v.x * v.x + v.y * v.y + v.z * v.z + v.w * v.w;
#pragma unroll
    for (int o = 16; o; o >>= 1) {
        s += __shfl_xor_sync(0xffffffffu, s, o);
        sq += __shfl_xor_sync(0xffffffffu, sq, o);
    }
    if ((tid & 31) == 0) red[tid >> 5] = make_float2(s, sq);
    __syncthreads();
    if (tid == 0) {
        float2 t = make_float2(0.f, 0.f);
        for (int i = 0; i < 8; i++) { t.x += red[i].x; t.y += red[i].y; }
        int b = cta >> 7;
        ps[b * 128 + (cta & 127)] = t;
    }
}

// ---------------- finalize: 128 partials per batch -> (mu, rstd) ----------
__global__ void finalize_k(const float2* __restrict__ ps, float* __restrict__ stats) {
    __shared__ float2 sh[8];
    int tid = threadIdx.x;
    int b = tid >> 7;
    float2 p = ps[b * 128 + (tid & 127)];
    float s = p.x, sq = p.y;
#pragma unroll
    for (int o = 16; o; o >>= 1) {
        s += __shfl_xor_sync(0xffffffffu, s, o);
        sq += __shfl_xor_sync(0xffffffffu, sq, o);
    }
    if ((tid & 31) == 0) sh[tid >> 5] = make_float2(s, sq);
    __syncthreads();
    if (tid < 2) {
        float ss = 0.f, ssq = 0.f;
        for (int i = 0; i < 4; i++) { ss += sh[tid * 4 + i].x; ssq += sh[tid * 4 + i].y; }
        float inv = 1.0f / (float)(TT_ * H_);
        float mu = ss * inv;
        float var = ssq * inv - mu * mu;
        stats[tid * 2] = mu;
        stats[tid * 2 + 1] = rsqrtf(var + EPS_);
    }
}

// ============ fused logits: 32t x 256a tile, h-chunk 64, dup'd smem =======
__global__ void logits_k(const float* __restrict__ tpart, const float* __restrict__ apart,
                         const float* __restrict__ w2, float* __restrict__ Lp) {
    __shared__ float Tsd[32][66];
    __shared__ float Am[32][258];
    __shared__ float wsd[66];
    int tid = threadIdx.x;
    int a0 = blockIdx.x * 256;
    int t0 = blockIdx.y * 32;
    int b  = blockIdx.z >> 4;
    int hc = blockIdx.z & 15;
    int h0 = hc * HCHUNK;
    int ty = tid >> 5;
    int tx = tid & 31;

    const float* Tp = tpart + (b * TT_ + t0) * H_ + h0;
    const float* Ap = apart + (b * TA_ + a0) * H_ + h0;
    const float* Wp = w2 + h0;

    int t_r = tid >> 3;
    int t_c = (tid & 7) * 4;

    u64 acc[4][4] = {};
    for (int hb = 0; hb < HCHUNK; hb += 32) {
        float4 tv = *reinterpret_cast<const float4*>(&Tp[t_r * H_ + hb + t_c]);
        Tsd[t_c + 0][2 * t_r] = tv.x; Tsd[t_c + 0][2 * t_r + 1] = tv.x;
        Tsd[t_c + 1][2 * t_r] = tv.y; Tsd[t_c + 1][2 * t_r + 1] = tv.y;
        Tsd[t_c + 2][2 * t_r] = tv.z; Tsd[t_c + 2][2 * t_r + 1] = tv.z;
        Tsd[t_c + 3][2 * t_r] = tv.w; Tsd[t_c + 3][2 * t_r + 1] = tv.w;
#pragma unroll
        for (int l = 0; l < 8; l++) {
            float4 av = *reinterpret_cast<const float4*>(&Ap[tid * H_ + hb + l * 4]);
            Am[l * 4 + 0][tid] = av.x;
            Am[l * 4 + 1][tid] = av.y;
            Am[l * 4 + 2][tid] = av.z;
            Am[l * 4 + 3][tid] = av.w;
        }
        if (tid < 32) {
            float w = Wp[hb + tid];
            wsd[2 * tid] = w; wsd[2 * tid + 1] = w;
        }
        __syncthreads();
#pragma unroll
        for (int hh = 0; hh < 32; hh++) {
            u64 wd = *reinterpret_cast<const u64*>(&wsd[2 * hh]);
            u64 ap0 = *reinterpret_cast<const u64*>(&Am[hh][2 * tx]);
            u64 ap1 = *reinterpret_cast<const u64*>(&Am[hh][64 + 2 * tx]);
            u64 ap2 = *reinterpret_cast<const u64*>(&Am[hh][128 + 2 * tx]);
            u64 ap3 = *reinterpret_cast<const u64*>(&Am[hh][192 + 2 * tx]);
#pragma unroll
            for (int i = 0; i < 4; i++) {
                u64 td = *reinterpret_cast<const u64*>(&Tsd[hh][2 * (ty + 8 * i)]);
                ffma2(acc[i][0], relu2(fadd2(td, ap0)), wd);
                ffma2(acc[i][1], relu2(fadd2(td, ap1)), wd);
                ffma2(acc[i][2], relu2(fadd2(td, ap2)), wd);
                ffma2(acc[i][3], relu2(fadd2(td, ap3)), wd);
            }
        }
        __syncthreads();
    }
    float* L = Lp + hc * (B_ * TT_ * TA_) + (b * TT_ + t0) * TA_ + a0;
#pragma unroll
    for (int i = 0; i < 4; i++) {
        int r = ty + 8 * i;
#pragma unroll
        for (int j = 0; j < 4; j++) {
            float2 p = unpack2(acc[i][j]);
            *reinterpret_cast<float2*>(&L[r * TA_ + j * 64 + 2 * tx]) = p;
        }
    }
}

// ---------------- softmax: sum 16 partials + monotonic bias ----------------
__global__ void softmax_k(const float* __restrict__ Lp, float* __restrict__ out) {
    __shared__ float wred[16];
    __shared__ float s_bcast;
    int row = blockIdx.x;
    int t = row & (TT_ - 1);
    int tid = threadIdx.x;
    const float* p = Lp + row * TA_ + tid;
    float v = 0.f;
#pragma unroll
    for (int hcx = 0; hcx < HSPLIT; hcx++)
        v += p[hcx * (B_ * TT_ * TA_)];
    v += -0.1f * fabsf((float)tid - (float)t * 4.0f);

    float m = v;
#pragma unroll
    for (int o = 16; o; o >>= 1) m = fmaxf(m, __shfl_xor_sync(0xffffffffu, m, o));
    if ((tid & 31) == 0) wred[tid >> 5] = m;
    __syncthreads();
    if (tid == 0) {
        float mm = wred[0];
        for (int i = 1; i < 16; i++) mm = fmaxf(mm, wred[i]);
        s_bcast = mm;
    }
    __syncthreads();
    float mx = s_bcast;
    float e = expf(v - mx);
    float s = e;
#pragma unroll
    for (int o = 16; o; o >>= 1) s += __shfl_xor_sync(0xffffffffu, s, o);
    if ((tid & 31) == 0) wred[tid >> 5] = s;
    __syncthreads();
    if (tid == 0) {
        float ss = 0.f;
        for (int i = 0; i < 16; i++) ss += wred[i];
        s_bcast = ss;
    }
    __syncthreads();
    out[row * TA_ + tid] = e / s_bcast;
}

// ---------------- duration head: GN2 + 1x1 conv + softplus ----------------
__global__ void dur_k(const float* __restrict__ X2, const float* __restrict__ w3,
                      const float* __restrict__ b3,
                      const float* __restrict__ gng, const float* __restrict__ gnb,
                      const float* __restrict__ stats, float* __restrict__ out) {
    __shared__ float wred[8];
    int bt = blockIdx.x;
    int b = bt / TT_;
    float mu = stats[b * 2], rstd = stats[b * 2 + 1];
    const float* x = X2 + bt * H_;
    int tid = threadIdx.x;
    float s = 0.f;
    for (int i = tid; i < H_; i += 256) {
        float v = (x[i] - mu) * rstd * gng[i] + gnb[i];
        s += v * w3[i];
    }
#pragma unroll
    for (int o = 16; o; o >>= 1) s += __shfl_xor_sync(0xffffffffu, s, o);
    if ((tid & 31) == 0) wred[tid >> 5] = s;
    __syncthreads();
    if (tid == 0) {
        float ss = 0.f;
        for (int i = 0; i < 8; i++) ss += wred[i];
        float z = ss + b3[0];
        out[bt] = fmaxf(z, 0.f) + log1pf(expf(-fabsf(z)));
    }
}

// ---------------- launch ----------------
extern "C" void kernel_launch(void* const* d_in, const int* in_sizes, int n_in,
                              void* d_out, int out_size) {
    (void)in_sizes; (void)n_in; (void)out_size;
    const float* text  = (const float*)d_in[0];
    const float* audio = (const float*)d_in[1];
    const float* a_w1  = (const float*)d_in[2];
    const float* a_b1  = (const float*)d_in[3];
    const float* a_w2  = (const float*)d_in[4];
    const float* d_w1  = (const float*)d_in[6];
    const float* d_b1  = (const float*)d_in[7];
    const float* gn1g  = (const float*)d_in[8];
    const float* gn1b  = (const float*)d_in[9];
    const float* d_w2  = (const float*)d_in[10];
    const float* d_b2  = (const float*)d_in[11];
    const float* gn2g  = (const float*)d_in[12];
    const float* gn2b  = (const float*)d_in[13];
    const float* d_w3  = (const float*)d_in[14];
    const float* d_b3  = (const float*)d_in[15];
    float* out = (float*)d_out;

    float *tpart, *apart, *cpA, *cpT, *x1, *x2, *cp, *lp, *stats, *w1t, *w2t;
    float2* ps;
    cudaGetSymbolAddress((void**)&tpart,  g_tpart);
    cudaGetSymbolAddress((void**)&apart,  g_apart);
    cudaGetSymbolAddress((void**)&cpA,    g_cpA);
    cudaGetSymbolAddress((void**)&cpT,    g_cpT);
    cudaGetSymbolAddress((void**)&x1,     g_x1);
    cudaGetSymbolAddress((void**)&x2,     g_x2);
    cudaGetSymbolAddress((void**)&cp,     g_cp);
    cudaGetSymbolAddress((void**)&lp,     g_lp);
    cudaGetSymbolAddress((void**)&stats,  g_stats);
    cudaGetSymbolAddress((void**)&ps,     g_ps);
    cudaGetSymbolAddress((void**)&w1t,    g_w1t);
    cudaGetSymbolAddress((void**)&w2t,    g_w2t);

    cudaStream_t s1, s2;
    cudaStreamCreateWithFlags(&s1, cudaStreamNonBlocking);
    cudaStreamCreateWithFlags(&s2, cudaStreamNonBlocking);
    cudaEvent_t evFork, e1, e2, e3;
    cudaEventCreateWithFlags(&evFork, cudaEventDisableTiming);
    cudaEventCreateWithFlags(&e1, cudaEventDisableTiming);
    cudaEventCreateWithFlags(&e2, cudaEventDisableTiming);
    cudaEventCreateWithFlags(&e3, cudaEventDisableTiming);
    cudaEventRecord(evFork, 0);
    cudaStreamWaitEvent(s1, evFork, 0);
    cudaStreamWaitEvent(s2, evFork, 0);

    dim3 tb(32, 8);
    dim3 tg(H_ / 32, H_ / 32);

    // s1: transpose w2 (for conv2), then tpart (K-split 4) + combine
    transpose_w_k<<<tg, tb, 0, s1>>>(d_w2, w2t);
    cudaEventRecord(e3, s1);
    gemm128s_k<<<dim3(H_ / 128, (B_ * TT_) / 128, 4), 256, 0, s1>>>(
        text, a_w1, cpT, B_ * TT_, H_, H_);
    combine4_k<true><<<(B_ * TT_ * H_) / 1024, 256, 0, s1>>>(
        cpT, a_b1, tpart, B_ * TT_ * H_);
    cudaEventRecord(e1, s1);

    // main: apart (K-split 4, 256 CTAs) + combine
    gemm128s_k<<<dim3(H_ / 128, (B_ * TA_) / 128, 4), 256>>>(
        audio, a_w1 + H_ * H_, cpA, B_ * TA_, H_, H_);
    combine4_k<false><<<(B_ * TA_ * H_) / 1024, 256>>>(
        cpA, nullptr, apart, B_ * TA_ * H_);

    // s2: duration path (conv tap x Ksplit = 192 CTAs each)
    transpose_w_k<<<tg, tb, 0, s2>>>(d_w1, w1t);
    convt128_k<false><<<dim3(H_ / 128, (B_ * TT_) / 128, 12), 256, 0, s2>>>(
        text, w1t, nullptr, nullptr, nullptr, cp);
    combine12_k<<<256, 256, 0, s2>>>(cp, d_b1, x1, ps);
    finalize_k<<<1, 256, 0, s2>>>(ps, stats);
    cudaStreamWaitEvent(s2, e3, 0);
    convt128_k<true><<<dim3(H_ / 128, (B_ * TT_) / 128, 12), 256, 0, s2>>>(
        x1, w2t, gn1g, gn1b, stats, cp);
    combine12_k<<<256, 256, 0, s2>>>(cp, d_b2, x2, ps + B_ * 128);
    finalize_k<<<1, 256, 0, s2>>>(ps + B_ * 128, stats + 4);
    dur_k<<<B_ * TT_, 256, 0, s2>>>(x2, d_w3, d_b3, gn2g, gn2b, stats + 4,
                                    out + B_ * TT_ * TA_);
    cudaEventRecord(e2, s2);

    // main: logits after tpart (e1) + apart (in-stream)
    cudaStreamWaitEvent(0, e1, 0);
    logits_k<<<dim3(TA_ / 256, TT_ / 32, B_ * HSPLIT), 256>>>(tpart, apart, a_w2, lp);
    softmax_k<<<B_ * TT_, TA_>>>(lp, out);

    cudaStreamWaitEvent(0, e2, 0);

    cudaEventDestroy(evFork);
    cudaEventDestroy(e1);
    cudaEventDestroy(e2);
    cudaEventDestroy(e3);
    cudaStreamDestroy(s1);
    cudaStreamDestroy(s2);
}